// round 3
// baseline (speedup 1.0000x reference)
#include <cuda_runtime.h>
#include <math.h>

// Problem constants
#define Bc 2
#define Lc 2048
#define Sc 2048
#define Dc 1024
#define Hc 16
#define NSc 8
#define NSLOTc 512
#define HDc 64

// ---------------- scratch (device globals; no allocation allowed) ----------------
__device__ float g_mem[NSLOTc * Dc];                 // ln_kv(E_slots)
__device__ float g_ek[NSLOTc * Dc];                  // mem @ Wk^T
__device__ float g_ev[NSLOTc * Dc];                  // mem @ Wv^T
__device__ float g_gkv[Sc * Dc];                     // silu(c_kv @ Wpe^T)
__device__ float g_K[(size_t)Bc * Sc * Dc];          // gathered+gated K
__device__ float g_V[(size_t)Bc * Sc * Dc];          // gathered+gated V
__device__ float g_xh[(size_t)Bc * Lc * Dc];         // ln_q(x_q * gate_q)
__device__ float g_Q[(size_t)Bc * Lc * Dc];          // xh @ Wq^T
__device__ float g_ao[(size_t)Bc * Lc * Dc];         // attention output

// ---------------- block reduce helper ----------------
__device__ __forceinline__ float blockReduceSum(float v, float* red) {
    int tid = threadIdx.x;
    int lane = tid & 31, w = tid >> 5;
#pragma unroll
    for (int o = 16; o; o >>= 1) v += __shfl_xor_sync(0xffffffffu, v, o);
    if (lane == 0) red[w] = v;
    __syncthreads();
    if (tid == 0) {
        float s = 0.f;
#pragma unroll
        for (int i = 0; i < 8; i++) s += red[i];
        red[0] = s;
    }
    __syncthreads();
    float r = red[0];
    __syncthreads();
    return r;
}

// ---------------- 1) layernorm rows (E_slots -> g_mem) ----------------
__global__ void ln_rows_kernel(const float* __restrict__ X, const float* __restrict__ gw,
                               const float* __restrict__ bw, float* __restrict__ Y) {
    __shared__ float red[8];
    int r = blockIdx.x, tid = threadIdx.x;
    const float* xr = X + (size_t)r * Dc;
    float4 x = *(const float4*)(xr + tid * 4);
    float mean = blockReduceSum(x.x + x.y + x.z + x.w, red) * (1.0f / Dc);
    float d0 = x.x - mean, d1 = x.y - mean, d2 = x.z - mean, d3 = x.w - mean;
    float var = blockReduceSum(d0 * d0 + d1 * d1 + d2 * d2 + d3 * d3, red) * (1.0f / Dc);
    float rs = rsqrtf(var + 1e-5f);
    float4 g4 = *(const float4*)(gw + tid * 4);
    float4 b4 = *(const float4*)(bw + tid * 4);
    float4 y = make_float4(d0 * rs * g4.x + b4.x, d1 * rs * g4.y + b4.y,
                           d2 * rs * g4.z + b4.z, d3 * rs * g4.w + b4.w);
    *(float4*)(Y + (size_t)r * Dc + tid * 4) = y;
}

// ---------------- 2) gate_kv[s,d] = silu( sum_m rho_m^(S-1-s) * Wpe[d,m] ) ----------------
__global__ void gatekv_kernel(const float* __restrict__ rhos, const float* __restrict__ Wpe) {
    __shared__ float c[NSc];
    int s = blockIdx.x, tid = threadIdx.x;
    if (tid < NSc) {
        double age = (double)(Sc - 1 - s);
        c[tid] = (float)exp(age * log((double)rhos[tid]));
    }
    __syncthreads();
    float cc[NSc];
#pragma unroll
    for (int m = 0; m < NSc; m++) cc[m] = c[m];
    float out[4];
#pragma unroll
    for (int e = 0; e < 4; e++) {
        int d = tid * 4 + e;
        const float* w = Wpe + (size_t)d * NSc;
        float t = 0.f;
#pragma unroll
        for (int m = 0; m < NSc; m++) t += cc[m] * w[m];
        out[e] = t / (1.0f + __expf(-t));
    }
    *(float4*)(g_gkv + (size_t)s * Dc + tid * 4) = make_float4(out[0], out[1], out[2], out[3]);
}

// ---------------- 3) gather + gate: K/V[b,s,:] = E{k,v}[idx]*gate_kv[s] ----------------
__global__ void gather_kernel(const int* __restrict__ xidx) {
    int bs = blockIdx.x, tid = threadIdx.x;
    int s = bs & (Sc - 1);
    int idx = xidx[bs];
    const float4* ek = (const float4*)g_ek + (size_t)idx * (Dc / 4);
    const float4* ev = (const float4*)g_ev + (size_t)idx * (Dc / 4);
    const float4* gk = (const float4*)g_gkv + (size_t)s * (Dc / 4);
    float4 w = gk[tid];
    float4 a = ek[tid];
    float4 b = ev[tid];
    float4* K4 = (float4*)g_K + (size_t)bs * (Dc / 4);
    float4* V4 = (float4*)g_V + (size_t)bs * (Dc / 4);
    K4[tid] = make_float4(a.x * w.x, a.y * w.y, a.z * w.z, a.w * w.w);
    V4[tid] = make_float4(b.x * w.x, b.y * w.y, b.z * w.z, b.w * w.w);
}

// ---------------- 4) xh = ln_q( x_q * silu(C_seq @ Wpe^T) ) ----------------
__global__ void gateq_ln_kernel(const float* __restrict__ xq, const float* __restrict__ Cs,
                                const float* __restrict__ Wpe,
                                const float* __restrict__ gw, const float* __restrict__ bw) {
    __shared__ float red[8];
    __shared__ float c[NSc];
    int r = blockIdx.x, tid = threadIdx.x;
    if (tid < NSc) c[tid] = Cs[(size_t)r * NSc + tid];
    __syncthreads();
    float cc[NSc];
#pragma unroll
    for (int m = 0; m < NSc; m++) cc[m] = c[m];
    float4 x = *(const float4*)(xq + (size_t)r * Dc + tid * 4);
    float xv[4] = {x.x, x.y, x.z, x.w};
    float y[4];
#pragma unroll
    for (int e = 0; e < 4; e++) {
        int d = tid * 4 + e;
        const float* w = Wpe + (size_t)d * NSc;
        float t = 0.f;
#pragma unroll
        for (int m = 0; m < NSc; m++) t += cc[m] * w[m];
        y[e] = xv[e] * (t / (1.0f + __expf(-t)));
    }
    float mean = blockReduceSum(y[0] + y[1] + y[2] + y[3], red) * (1.0f / Dc);
#pragma unroll
    for (int e = 0; e < 4; e++) y[e] -= mean;
    float var = blockReduceSum(y[0] * y[0] + y[1] * y[1] + y[2] * y[2] + y[3] * y[3], red) * (1.0f / Dc);
    float rs = rsqrtf(var + 1e-5f);
    float4 g4 = *(const float4*)(gw + tid * 4);
    float4 b4 = *(const float4*)(bw + tid * 4);
    float4 o = make_float4(y[0] * rs * g4.x + b4.x, y[1] * rs * g4.y + b4.y,
                           y[2] * rs * g4.z + b4.z, y[3] * rs * g4.w + b4.w);
    *(float4*)(g_xh + (size_t)r * Dc + tid * 4) = o;
}

// ---------------- 5) GEMM: C[M,N] = A[M,K] * B[N,K]^T, all row-major, dims %64/%16 ----------------
__global__ void gemm_abt_kernel(const float* __restrict__ A, const float* __restrict__ Bm,
                                float* __restrict__ C, int M, int N, int K) {
    __shared__ float As[16][68];
    __shared__ float Bs[16][68];
    int tid = threadIdx.x;
    int ty = tid >> 4, tx = tid & 15;
    int row0 = blockIdx.y * 64, col0 = blockIdx.x * 64;
    int lr = tid >> 2;
    int lk = (tid & 3) * 4;
    const float* Ap = A + (size_t)(row0 + lr) * K + lk;
    const float* Bp = Bm + (size_t)(col0 + lr) * K + lk;
    float acc[4][4] = {};
    for (int k0 = 0; k0 < K; k0 += 16) {
        float4 av = *(const float4*)(Ap + k0);
        float4 bv = *(const float4*)(Bp + k0);
        As[lk + 0][lr] = av.x; As[lk + 1][lr] = av.y; As[lk + 2][lr] = av.z; As[lk + 3][lr] = av.w;
        Bs[lk + 0][lr] = bv.x; Bs[lk + 1][lr] = bv.y; Bs[lk + 2][lr] = bv.z; Bs[lk + 3][lr] = bv.w;
        __syncthreads();
#pragma unroll
        for (int kk = 0; kk < 16; kk++) {
            float4 a = *(const float4*)&As[kk][ty * 4];
            float4 b = *(const float4*)&Bs[kk][tx * 4];
            acc[0][0] += a.x * b.x; acc[0][1] += a.x * b.y; acc[0][2] += a.x * b.z; acc[0][3] += a.x * b.w;
            acc[1][0] += a.y * b.x; acc[1][1] += a.y * b.y; acc[1][2] += a.y * b.z; acc[1][3] += a.y * b.w;
            acc[2][0] += a.z * b.x; acc[2][1] += a.z * b.y; acc[2][2] += a.z * b.z; acc[2][3] += a.z * b.w;
            acc[3][0] += a.w * b.x; acc[3][1] += a.w * b.y; acc[3][2] += a.w * b.z; acc[3][3] += a.w * b.w;
        }
        __syncthreads();
    }
#pragma unroll
    for (int i = 0; i < 4; i++) {
        *(float4*)(C + (size_t)(row0 + ty * 4 + i) * N + col0 + tx * 4) =
            make_float4(acc[i][0], acc[i][1], acc[i][2], acc[i][3]);
    }
}

// ---------------- 6) flash attention: 64-query x 64-key tiles, HD=64 ----------------
#define AW 68
__global__ void attn_kernel() {
    extern __shared__ float sm[];
    float* Qst = sm;                 // [64 d][AW]  (d-major, transposed Q tile)
    float* KP  = sm + 64 * AW;       // K tile d-major, then reused as P [key][AW]
    float* Vs  = sm + 2 * 64 * AW;   // [64 s][64 d] natural
    int b = blockIdx.y >> 4, h = blockIdx.y & 15;
    int q0 = blockIdx.x * 64;
    int tid = threadIdx.x, ty = tid >> 4, tx = tid & 15;
    int lr = tid >> 2;
    int lc = (tid & 3) * 16;
    const float* Qb = g_Q + ((size_t)b * Lc + q0) * Dc + h * HDc;
    const float* Kb = g_K + (size_t)b * Sc * Dc + h * HDc;
    const float* Vb = g_V + (size_t)b * Sc * Dc + h * HDc;
#pragma unroll
    for (int j = 0; j < 4; j++) {
        int d = lc + j * 4;
        float4 v = *(const float4*)(Qb + (size_t)lr * Dc + d);
        Qst[(d + 0) * AW + lr] = v.x; Qst[(d + 1) * AW + lr] = v.y;
        Qst[(d + 2) * AW + lr] = v.z; Qst[(d + 3) * AW + lr] = v.w;
    }
    float m[4], l[4], o[4][4];
#pragma unroll
    for (int i = 0; i < 4; i++) {
        m[i] = -1e30f; l[i] = 0.f;
#pragma unroll
        for (int j = 0; j < 4; j++) o[i][j] = 0.f;
    }
    for (int s0 = 0; s0 < Sc; s0 += 64) {
        __syncthreads();
#pragma unroll
        for (int j = 0; j < 4; j++) {
            int d = lc + j * 4;
            float4 kv = *(const float4*)(Kb + (size_t)(s0 + lr) * Dc + d);
            KP[(d + 0) * AW + lr] = kv.x; KP[(d + 1) * AW + lr] = kv.y;
            KP[(d + 2) * AW + lr] = kv.z; KP[(d + 3) * AW + lr] = kv.w;
            float4 vv = *(const float4*)(Vb + (size_t)(s0 + lr) * Dc + d);
            *(float4*)(Vs + lr * 64 + d) = vv;
        }
        __syncthreads();
        float p[4][4] = {};
#pragma unroll 16
        for (int d = 0; d < 64; d++) {
            float4 a = *(const float4*)(Qst + d * AW + ty * 4);
            float4 bb = *(const float4*)(KP + d * AW + tx * 4);
            p[0][0] += a.x * bb.x; p[0][1] += a.x * bb.y; p[0][2] += a.x * bb.z; p[0][3] += a.x * bb.w;
            p[1][0] += a.y * bb.x; p[1][1] += a.y * bb.y; p[1][2] += a.y * bb.z; p[1][3] += a.y * bb.w;
            p[2][0] += a.z * bb.x; p[2][1] += a.z * bb.y; p[2][2] += a.z * bb.z; p[2][3] += a.z * bb.w;
            p[3][0] += a.w * bb.x; p[3][1] += a.w * bb.y; p[3][2] += a.w * bb.z; p[3][3] += a.w * bb.w;
        }
#pragma unroll
        for (int i = 0; i < 4; i++) {
#pragma unroll
            for (int j = 0; j < 4; j++) p[i][j] *= 0.125f;  // 1/sqrt(64)
            float rmax = fmaxf(fmaxf(p[i][0], p[i][1]), fmaxf(p[i][2], p[i][3]));
#pragma unroll
            for (int off = 1; off < 16; off <<= 1)
                rmax = fmaxf(rmax, __shfl_xor_sync(0xffffffffu, rmax, off));
            float mn = fmaxf(m[i], rmax);
            float al = __expf(m[i] - mn);
            float rs = 0.f;
#pragma unroll
            for (int j = 0; j < 4; j++) { p[i][j] = __expf(p[i][j] - mn); rs += p[i][j]; }
#pragma unroll
            for (int off = 1; off < 16; off <<= 1)
                rs += __shfl_xor_sync(0xffffffffu, rs, off);
            l[i] = l[i] * al + rs;
            m[i] = mn;
#pragma unroll
            for (int j = 0; j < 4; j++) o[i][j] *= al;
        }
        __syncthreads();
#pragma unroll
        for (int j = 0; j < 4; j++)
#pragma unroll
            for (int i = 0; i < 4; i++)
                KP[(tx * 4 + j) * AW + ty * 4 + i] = p[i][j];
        __syncthreads();
#pragma unroll 16
        for (int kk = 0; kk < 64; kk++) {
            float4 a = *(const float4*)(KP + kk * AW + ty * 4);
            float4 bb = *(const float4*)(Vs + kk * 64 + tx * 4);
            o[0][0] += a.x * bb.x; o[0][1] += a.x * bb.y; o[0][2] += a.x * bb.z; o[0][3] += a.x * bb.w;
            o[1][0] += a.y * bb.x; o[1][1] += a.y * bb.y; o[1][2] += a.y * bb.z; o[1][3] += a.y * bb.w;
            o[2][0] += a.z * bb.x; o[2][1] += a.z * bb.y; o[2][2] += a.z * bb.z; o[2][3] += a.z * bb.w;
            o[3][0] += a.w * bb.x; o[3][1] += a.w * bb.y; o[3][2] += a.w * bb.z; o[3][3] += a.w * bb.w;
        }
    }
    float* Ob = g_ao + ((size_t)b * Lc + q0) * Dc + h * HDc;
#pragma unroll
    for (int i = 0; i < 4; i++) {
        float inv = 1.0f / l[i];
        *(float4*)(Ob + (size_t)(ty * 4 + i) * Dc + tx * 4) =
            make_float4(o[i][0] * inv, o[i][1] * inv, o[i][2] * inv, o[i][3] * inv);
    }
}

// ---------------- launch ----------------
extern "C" void kernel_launch(void* const* d_in, const int* in_sizes, int n_in,
                              void* d_out, int out_size) {
    const float* x_q  = (const float*)d_in[0];
    const int*   xidx = (const int*)d_in[1];
    const float* E    = (const float*)d_in[2];
    const float* rhos = (const float*)d_in[3];
    const float* Cs   = (const float*)d_in[4];
    const float* Wq   = (const float*)d_in[5];
    const float* Wk   = (const float*)d_in[6];
    const float* Wv   = (const float*)d_in[7];
    const float* Wo   = (const float*)d_in[8];
    const float* Wpe  = (const float*)d_in[9];
    const float* lnkg = (const float*)d_in[10];
    const float* lnkb = (const float*)d_in[11];
    const float* lnqg = (const float*)d_in[12];
    const float* lnqb = (const float*)d_in[13];
    float* out = (float*)d_out;

    float *p_mem, *p_ek, *p_ev, *p_xh, *p_Q, *p_ao;
    cudaGetSymbolAddress((void**)&p_mem, g_mem);
    cudaGetSymbolAddress((void**)&p_ek, g_ek);
    cudaGetSymbolAddress((void**)&p_ev, g_ev);
    cudaGetSymbolAddress((void**)&p_xh, g_xh);
    cudaGetSymbolAddress((void**)&p_Q, g_Q);
    cudaGetSymbolAddress((void**)&p_ao, g_ao);

    // KV side
    ln_rows_kernel<<<NSLOTc, 256>>>(E, lnkg, lnkb, p_mem);
    gemm_abt_kernel<<<dim3(Dc / 64, NSLOTc / 64), 256>>>(p_mem, Wk, p_ek, NSLOTc, Dc, Dc);
    gemm_abt_kernel<<<dim3(Dc / 64, NSLOTc / 64), 256>>>(p_mem, Wv, p_ev, NSLOTc, Dc, Dc);
    gatekv_kernel<<<Sc, 256>>>(rhos, Wpe);
    gather_kernel<<<Bc * Sc, 256>>>(xidx);

    // Q side
    gateq_ln_kernel<<<Bc * Lc, 256>>>(x_q, Cs, Wpe, lnqg, lnqb);
    gemm_abt_kernel<<<dim3(Dc / 64, (Bc * Lc) / 64), 256>>>(p_xh, Wq, p_Q, Bc * Lc, Dc, Dc);

    // Attention
    const int attn_smem = (2 * 64 * AW + 64 * 64) * (int)sizeof(float);  // 51200 B
    cudaFuncSetAttribute(attn_kernel, cudaFuncAttributeMaxDynamicSharedMemorySize, attn_smem);
    attn_kernel<<<dim3(Lc / 64, Bc * Hc), 256, attn_smem>>>();

    // Output projection
    gemm_abt_kernel<<<dim3(Dc / 64, (Bc * Lc) / 64), 256>>>(p_ao, Wo, out, Bc * Lc, Dc, Dc);
}

// round 4
// speedup vs baseline: 1.8427x; 1.8427x over previous
#include <cuda_runtime.h>
#include <cuda_bf16.h>
#include <math.h>
#include <stdint.h>

#define Bc 2
#define Lc 2048
#define Sc 2048
#define Dc 1024
#define Hc 16
#define NSc 8
#define NSLOTc 512
#define HDc 64
#define BLc (Bc*Lc)
#define BSc (Bc*Sc)

typedef __nv_bfloat16 bf16;
typedef __nv_bfloat162 bf162;

// ---------------- scratch ----------------
__device__ __align__(16) bf16 g_Wqh[Dc*Dc], g_Wql[Dc*Dc];
__device__ __align__(16) bf16 g_Wkh[Dc*Dc], g_Wkl[Dc*Dc];
__device__ __align__(16) bf16 g_Wvh[Dc*Dc], g_Wvl[Dc*Dc];
__device__ __align__(16) bf16 g_Woh[Dc*Dc], g_Wol[Dc*Dc];
__device__ __align__(16) bf16 g_memh[NSLOTc*Dc], g_meml[NSLOTc*Dc];
__device__ __align__(16) float g_ek[NSLOTc*Dc], g_ev[NSLOTc*Dc];
__device__ __align__(16) float g_ctab[Sc*NSc];
__device__ __align__(16) bf16 g_Kh[(size_t)BSc*Dc], g_Kl[(size_t)BSc*Dc];
__device__ __align__(16) bf16 g_Vh[(size_t)BSc*Dc], g_Vl[(size_t)BSc*Dc];
__device__ __align__(16) bf16 g_xhh[(size_t)BLc*Dc], g_xhl[(size_t)BLc*Dc];
__device__ __align__(16) bf16 g_Qh[(size_t)BLc*Dc], g_Ql[(size_t)BLc*Dc];
__device__ __align__(16) bf16 g_aoh[(size_t)BLc*Dc], g_aol[(size_t)BLc*Dc];

// ---------------- helpers ----------------
__device__ __forceinline__ uint32_t smem_u32(const void* p) {
    return (uint32_t)__cvta_generic_to_shared(p);
}
__device__ __forceinline__ void ldsm_x4(uint32_t* r, uint32_t a) {
    asm volatile("ldmatrix.sync.aligned.m8n8.x4.shared.b16 {%0,%1,%2,%3}, [%4];"
                 : "=r"(r[0]), "=r"(r[1]), "=r"(r[2]), "=r"(r[3]) : "r"(a));
}
__device__ __forceinline__ void ldsm_x4t(uint32_t* r, uint32_t a) {
    asm volatile("ldmatrix.sync.aligned.m8n8.x4.trans.shared.b16 {%0,%1,%2,%3}, [%4];"
                 : "=r"(r[0]), "=r"(r[1]), "=r"(r[2]), "=r"(r[3]) : "r"(a));
}
__device__ __forceinline__ void mma_(float* c, const uint32_t* a, uint32_t b0, uint32_t b1) {
    asm volatile("mma.sync.aligned.m16n8k16.row.col.f32.bf16.bf16.f32 "
                 "{%0,%1,%2,%3},{%4,%5,%6,%7},{%8,%9},{%0,%1,%2,%3};"
                 : "+f"(c[0]), "+f"(c[1]), "+f"(c[2]), "+f"(c[3])
                 : "r"(a[0]), "r"(a[1]), "r"(a[2]), "r"(a[3]), "r"(b0), "r"(b1));
}
__device__ __forceinline__ void mma3(float* c, const uint32_t* ah, const uint32_t* al,
                                     uint32_t bh0, uint32_t bh1, uint32_t bl0, uint32_t bl1) {
    mma_(c, ah, bh0, bh1); mma_(c, ah, bl0, bl1); mma_(c, al, bh0, bh1);
}
__device__ __forceinline__ void cpa16(uint32_t s, const void* g) {
    asm volatile("cp.async.cg.shared.global [%0], [%1], 16;" :: "r"(s), "l"(g));
}
__device__ __forceinline__ void cpa_commit() { asm volatile("cp.async.commit_group;"); }
__device__ __forceinline__ void sst2(bf16* H, bf16* L, size_t o, float x, float y) {
    bf162 h = __floats2bfloat162_rn(x, y);
    bf162 l = __floats2bfloat162_rn(x - __bfloat162float(h.x), y - __bfloat162float(h.y));
    *(bf162*)(H + o) = h; *(bf162*)(L + o) = l;
}
__device__ __forceinline__ void splitpack(float x, float y, uint32_t& h, uint32_t& l) {
    bf162 hh = __floats2bfloat162_rn(x, y);
    bf162 ll = __floats2bfloat162_rn(x - __bfloat162float(hh.x), y - __bfloat162float(hh.y));
    h = *(uint32_t*)&hh; l = *(uint32_t*)&ll;
}
__device__ __forceinline__ float blockReduceSum(float v, float* red) {
    int tid = threadIdx.x, lane = tid & 31, w = tid >> 5;
#pragma unroll
    for (int o = 16; o; o >>= 1) v += __shfl_xor_sync(0xffffffffu, v, o);
    if (lane == 0) red[w] = v;
    __syncthreads();
    if (tid == 0) {
        float s = 0.f;
#pragma unroll
        for (int i = 0; i < 8; i++) s += red[i];
        red[0] = s;
    }
    __syncthreads();
    float r = red[0];
    __syncthreads();
    return r;
}

// ---------------- elementwise kernels ----------------
__global__ void split_w_kernel(const float* __restrict__ src, bf16* __restrict__ h,
                               bf16* __restrict__ l, int n2) {
    int i = blockIdx.x * blockDim.x + threadIdx.x;
    if (i >= n2) return;
    float2 v = ((const float2*)src)[i];
    bf162 hh = __floats2bfloat162_rn(v.x, v.y);
    bf162 ll = __floats2bfloat162_rn(v.x - __bfloat162float(hh.x), v.y - __bfloat162float(hh.y));
    ((bf162*)h)[i] = hh; ((bf162*)l)[i] = ll;
}

__global__ void ln_rows_kernel(const float* __restrict__ X, const float* __restrict__ gw,
                               const float* __restrict__ bw,
                               bf16* __restrict__ Yh, bf16* __restrict__ Yl) {
    __shared__ float red[8];
    int r = blockIdx.x, tid = threadIdx.x;
    float4 x = *(const float4*)(X + (size_t)r * Dc + tid * 4);
    float mean = blockReduceSum(x.x + x.y + x.z + x.w, red) * (1.0f / Dc);
    float d0 = x.x - mean, d1 = x.y - mean, d2 = x.z - mean, d3 = x.w - mean;
    float var = blockReduceSum(d0*d0 + d1*d1 + d2*d2 + d3*d3, red) * (1.0f / Dc);
    float rs = rsqrtf(var + 1e-5f);
    float4 g4 = *(const float4*)(gw + tid * 4);
    float4 b4 = *(const float4*)(bw + tid * 4);
    size_t o = (size_t)r * Dc + tid * 4;
    sst2(Yh, Yl, o,     d0*rs*g4.x + b4.x, d1*rs*g4.y + b4.y);
    sst2(Yh, Yl, o + 2, d2*rs*g4.z + b4.z, d3*rs*g4.w + b4.w);
}

__global__ void ctab_kernel(const float* __restrict__ rhos) {
    int i = blockIdx.x * blockDim.x + threadIdx.x;
    if (i >= Sc * NSc) return;
    int s = i >> 3, m = i & 7;
    double age = (double)(Sc - 1 - s);
    g_ctab[i] = (float)exp(age * log((double)rhos[m]));
}

__global__ void gather_kernel(const int* __restrict__ xidx, const float* __restrict__ Wpe) {
    __shared__ float c[NSc];
    int bs = blockIdx.x, tid = threadIdx.x;
    int s = bs & (Sc - 1);
    int idx = xidx[bs];
    if (tid < NSc) c[tid] = g_ctab[s * NSc + tid];
    __syncthreads();
    float cc[NSc];
#pragma unroll
    for (int m = 0; m < NSc; m++) cc[m] = c[m];
    float4 ek4 = ((const float4*)(g_ek + (size_t)idx * Dc))[tid];
    float4 ev4 = ((const float4*)(g_ev + (size_t)idx * Dc))[tid];
    float kx[4] = {ek4.x, ek4.y, ek4.z, ek4.w};
    float vx[4] = {ev4.x, ev4.y, ev4.z, ev4.w};
#pragma unroll
    for (int e = 0; e < 4; e++) {
        const float* w = Wpe + (size_t)(tid * 4 + e) * NSc;
        float t = 0.f;
#pragma unroll
        for (int m = 0; m < NSc; m++) t += cc[m] * w[m];
        float g = t / (1.0f + __expf(-t));
        kx[e] *= g; vx[e] *= g;
    }
    size_t o = (size_t)bs * Dc + tid * 4;
    sst2(g_Kh, g_Kl, o, kx[0], kx[1]); sst2(g_Kh, g_Kl, o + 2, kx[2], kx[3]);
    sst2(g_Vh, g_Vl, o, vx[0], vx[1]); sst2(g_Vh, g_Vl, o + 2, vx[2], vx[3]);
}

__global__ void gateq_ln_kernel(const float* __restrict__ xq, const float* __restrict__ Cs,
                                const float* __restrict__ Wpe,
                                const float* __restrict__ gw, const float* __restrict__ bw) {
    __shared__ float red[8];
    __shared__ float c[NSc];
    int r = blockIdx.x, tid = threadIdx.x;
    if (tid < NSc) c[tid] = Cs[(size_t)r * NSc + tid];
    __syncthreads();
    float cc[NSc];
#pragma unroll
    for (int m = 0; m < NSc; m++) cc[m] = c[m];
    float4 x = *(const float4*)(xq + (size_t)r * Dc + tid * 4);
    float xv[4] = {x.x, x.y, x.z, x.w};
    float y[4];
#pragma unroll
    for (int e = 0; e < 4; e++) {
        const float* w = Wpe + (size_t)(tid * 4 + e) * NSc;
        float t = 0.f;
#pragma unroll
        for (int m = 0; m < NSc; m++) t += cc[m] * w[m];
        y[e] = xv[e] * (t / (1.0f + __expf(-t)));
    }
    float mean = blockReduceSum(y[0] + y[1] + y[2] + y[3], red) * (1.0f / Dc);
#pragma unroll
    for (int e = 0; e < 4; e++) y[e] -= mean;
    float var = blockReduceSum(y[0]*y[0] + y[1]*y[1] + y[2]*y[2] + y[3]*y[3], red) * (1.0f / Dc);
    float rs = rsqrtf(var + 1e-5f);
    float4 g4 = *(const float4*)(gw + tid * 4);
    float4 b4 = *(const float4*)(bw + tid * 4);
    size_t o = (size_t)r * Dc + tid * 4;
    sst2(g_xhh, g_xhl, o,     y[0]*rs*g4.x + b4.x, y[1]*rs*g4.y + b4.y);
    sst2(g_xhh, g_xhl, o + 2, y[2]*rs*g4.z + b4.z, y[3]*rs*g4.w + b4.w);
}

// ---------------- split-bf16 tensor-core GEMM: C[M,N] = A[M,K] * B[N,K]^T ----------------
// 128x128 tile, BK=32, 256 threads (8 warps 4m x 2n), double-buffered cp.async.
template<bool SPLITOUT>
__global__ __launch_bounds__(256)
void gemm_bs(const bf16* __restrict__ Ah, const bf16* __restrict__ Al,
             const bf16* __restrict__ Bh, const bf16* __restrict__ Bl,
             float* __restrict__ C, bf16* __restrict__ Ch, bf16* __restrict__ Cl,
             int M, int N, int K) {
    extern __shared__ char smraw[];
    const int RS = 80, TB = 128 * RS;
    int tid = threadIdx.x, lane = tid & 31, warp = tid >> 5;
    int wm = (warp >> 1) * 32, wn = (warp & 1) * 64;
    int row0 = blockIdx.y * 128, col0 = blockIdx.x * 128;
    int r_ld = tid >> 1;
    const bf16* gp[4];
    gp[0] = Ah + (size_t)(row0 + r_ld) * K + (tid & 1) * 16;
    gp[1] = Al + (size_t)(row0 + r_ld) * K + (tid & 1) * 16;
    gp[2] = Bh + (size_t)(col0 + r_ld) * K + (tid & 1) * 16;
    gp[3] = Bl + (size_t)(col0 + r_ld) * K + (tid & 1) * 16;
    uint32_t sb = smem_u32(smraw);
    uint32_t st = (uint32_t)(r_ld * RS + (tid & 1) * 32);
    auto load = [&](int bf, int k0) {
#pragma unroll
        for (int o = 0; o < 4; o++) {
            uint32_t s = sb + (uint32_t)((bf * 4 + o) * TB) + st;
            cpa16(s, gp[o] + k0); cpa16(s + 16, gp[o] + k0 + 8);
        }
        cpa_commit();
    };
    float acc[2][8][4] = {};
    int mrow = ((lane >> 3) & 1) * 8 + (lane & 7), mcb = (lane >> 4) * 16;
    const int KC = K / 32;
    load(0, 0);
    for (int kc = 0; kc < KC; kc++) {
        if (kc + 1 < KC) {
            load((kc + 1) & 1, (kc + 1) * 32);
            asm volatile("cp.async.wait_group 1;");
        } else {
            asm volatile("cp.async.wait_group 0;");
        }
        __syncthreads();
        uint32_t bo = sb + (uint32_t)((kc & 1) * 4 * TB);
#pragma unroll
        for (int ks = 0; ks < 2; ks++) {
            uint32_t ah[2][4], al[2][4];
#pragma unroll
            for (int i = 0; i < 2; i++) {
                uint32_t aa = bo + (uint32_t)((wm + i * 16 + mrow) * RS + ks * 32 + mcb);
                ldsm_x4(ah[i], aa); ldsm_x4(al[i], aa + TB);
            }
#pragma unroll
            for (int j2 = 0; j2 < 4; j2++) {
                uint32_t ba = bo + (uint32_t)(2 * TB + (wn + j2 * 16 + mrow) * RS + ks * 32 + mcb);
                uint32_t bh[4], bl[4];
                ldsm_x4(bh, ba); ldsm_x4(bl, ba + TB);
#pragma unroll
                for (int i = 0; i < 2; i++) {
                    mma3(acc[i][2 * j2],     ah[i], al[i], bh[0], bh[2], bl[0], bl[2]);
                    mma3(acc[i][2 * j2 + 1], ah[i], al[i], bh[1], bh[3], bl[1], bl[3]);
                }
            }
        }
        __syncthreads();
    }
    int r = lane >> 2, q = (lane & 3) * 2;
#pragma unroll
    for (int i = 0; i < 2; i++)
#pragma unroll
        for (int j = 0; j < 8; j++) {
            size_t g0 = (size_t)(row0 + wm + i * 16 + r) * N + col0 + wn + j * 8 + q;
            float* a = acc[i][j];
            if (SPLITOUT) {
                sst2(Ch, Cl, g0, a[0], a[1]);
                sst2(Ch, Cl, g0 + (size_t)8 * N, a[2], a[3]);
            } else {
                *(float2*)(C + g0) = make_float2(a[0], a[1]);
                *(float2*)(C + g0 + (size_t)8 * N) = make_float2(a[2], a[3]);
            }
        }
}

// ---------------- flash attention, tensor cores, split bf16 ----------------
// 128 threads = 4 warps; q-tile 64 (warp = m16); s-chunks of 64; HD=64.
__global__ __launch_bounds__(128)
void attn_kernel() {
    extern __shared__ char smraw[];
    const int RS = 144, TB = 64 * RS;  // tiles: 0 Qh,1 Ql,2 Kh,3 Kl,4 Vh,5 Vl
    uint32_t sb = smem_u32(smraw);
    int tid = threadIdx.x, lane = tid & 31, warp = tid >> 5;
    int b = blockIdx.y >> 4, h = blockIdx.y & 15;
    int q0 = blockIdx.x * 64;
    size_t qoff = ((size_t)(b * Lc + q0)) * Dc + h * HDc;
    size_t koff = ((size_t)b * Sc) * Dc + h * HDc;
    int r_ld = tid >> 1;
    uint32_t st = (uint32_t)(r_ld * RS + (tid & 1) * 64);
    size_t ldo = (size_t)r_ld * Dc + (tid & 1) * 32;
    // Q tile
    {
        const bf16* gq[2] = {g_Qh + qoff + ldo, g_Ql + qoff + ldo};
#pragma unroll
        for (int o = 0; o < 2; o++)
#pragma unroll
            for (int j = 0; j < 4; j++)
                cpa16(sb + (uint32_t)(o * TB) + st + j * 16, gq[o] + j * 8);
        cpa_commit();
        asm volatile("cp.async.wait_group 0;");
        __syncthreads();
    }
    int mrow = ((lane >> 3) & 1) * 8 + (lane & 7), mcb = (lane >> 4) * 16;
    uint32_t qh[4][4], ql[4][4];
#pragma unroll
    for (int ks = 0; ks < 4; ks++) {
        uint32_t a = sb + (uint32_t)((warp * 16 + mrow) * RS + ks * 32 + mcb);
        ldsm_x4(qh[ks], a); ldsm_x4(ql[ks], a + TB);
    }
    const bf16* gk[4] = {g_Kh + koff + ldo, g_Kl + koff + ldo,
                         g_Vh + koff + ldo, g_Vl + koff + ldo};
    float Oa[8][4] = {};
    float mr[2] = {-1e30f, -1e30f}, lr[2] = {0.f, 0.f};
    for (int sc = 0; sc < Sc / 64; sc++) {
        __syncthreads();
        size_t go = (size_t)sc * 64 * Dc;
#pragma unroll
        for (int o = 0; o < 4; o++)
#pragma unroll
            for (int j = 0; j < 4; j++)
                cpa16(sb + (uint32_t)((2 + o) * TB) + st + j * 16, gk[o] + go + j * 8);
        cpa_commit();
        asm volatile("cp.async.wait_group 0;");
        __syncthreads();
        // S = Q K^T
        float Sa[8][4] = {};
#pragma unroll
        for (int ks = 0; ks < 4; ks++)
#pragma unroll
            for (int j2 = 0; j2 < 4; j2++) {
                uint32_t ba = sb + (uint32_t)(2 * TB + (j2 * 16 + mrow) * RS + ks * 32 + mcb);
                uint32_t bh[4], bl[4];
                ldsm_x4(bh, ba); ldsm_x4(bl, ba + TB);
                mma3(Sa[2 * j2],     qh[ks], ql[ks], bh[0], bh[2], bl[0], bl[2]);
                mma3(Sa[2 * j2 + 1], qh[ks], ql[ks], bh[1], bh[3], bl[1], bl[3]);
            }
        // online softmax (two rows/thread: r = lane>>2, r+8)
        float mx[2] = {-1e30f, -1e30f};
#pragma unroll
        for (int j = 0; j < 8; j++) {
#pragma unroll
            for (int k = 0; k < 4; k++) Sa[j][k] *= 0.125f;
            mx[0] = fmaxf(mx[0], fmaxf(Sa[j][0], Sa[j][1]));
            mx[1] = fmaxf(mx[1], fmaxf(Sa[j][2], Sa[j][3]));
        }
        float al2[2];
#pragma unroll
        for (int t = 0; t < 2; t++) {
            mx[t] = fmaxf(mx[t], __shfl_xor_sync(0xffffffffu, mx[t], 1));
            mx[t] = fmaxf(mx[t], __shfl_xor_sync(0xffffffffu, mx[t], 2));
            float nm = fmaxf(mr[t], mx[t]);
            al2[t] = __expf(mr[t] - nm);
            mr[t] = nm;
        }
        float rs[2] = {0.f, 0.f};
#pragma unroll
        for (int j = 0; j < 8; j++) {
            Sa[j][0] = __expf(Sa[j][0] - mr[0]); Sa[j][1] = __expf(Sa[j][1] - mr[0]);
            Sa[j][2] = __expf(Sa[j][2] - mr[1]); Sa[j][3] = __expf(Sa[j][3] - mr[1]);
            rs[0] += Sa[j][0] + Sa[j][1]; rs[1] += Sa[j][2] + Sa[j][3];
            Oa[j][0] *= al2[0]; Oa[j][1] *= al2[0];
            Oa[j][2] *= al2[1]; Oa[j][3] *= al2[1];
        }
#pragma unroll
        for (int t = 0; t < 2; t++) {
            rs[t] += __shfl_xor_sync(0xffffffffu, rs[t], 1);
            rs[t] += __shfl_xor_sync(0xffffffffu, rs[t], 2);
            lr[t] = lr[t] * al2[t] + rs[t];
        }
        // O += P V  (P split in registers, FA2 C->A fragment identity)
#pragma unroll
        for (int kk = 0; kk < 4; kk++) {
            uint32_t ph[4], pl[4];
            splitpack(Sa[2 * kk][0],     Sa[2 * kk][1],     ph[0], pl[0]);
            splitpack(Sa[2 * kk][2],     Sa[2 * kk][3],     ph[1], pl[1]);
            splitpack(Sa[2 * kk + 1][0], Sa[2 * kk + 1][1], ph[2], pl[2]);
            splitpack(Sa[2 * kk + 1][2], Sa[2 * kk + 1][3], ph[3], pl[3]);
#pragma unroll
            for (int j2 = 0; j2 < 4; j2++) {
                uint32_t va = sb + (uint32_t)(4 * TB + (kk * 16 + (lane & 15)) * RS
                                              + j2 * 32 + (lane >> 4) * 16);
                uint32_t vh[4], vl[4];
                ldsm_x4t(vh, va); ldsm_x4t(vl, va + TB);
                mma3(Oa[2 * j2],     ph, pl, vh[0], vh[1], vl[0], vl[1]);
                mma3(Oa[2 * j2 + 1], ph, pl, vh[2], vh[3], vl[2], vl[3]);
            }
        }
    }
    float inv0 = 1.f / lr[0], inv1 = 1.f / lr[1];
    int r = lane >> 2, q = (lane & 3) * 2;
    size_t o0 = qoff + (size_t)(warp * 16 + r) * Dc;
#pragma unroll
    for (int j = 0; j < 8; j++) {
        sst2(g_aoh, g_aol, o0 + j * 8 + q, Oa[j][0] * inv0, Oa[j][1] * inv0);
        sst2(g_aoh, g_aol, o0 + (size_t)8 * Dc + j * 8 + q, Oa[j][2] * inv1, Oa[j][3] * inv1);
    }
}

// ---------------- launch ----------------
extern "C" void kernel_launch(void* const* d_in, const int* in_sizes, int n_in,
                              void* d_out, int out_size) {
    const float* x_q  = (const float*)d_in[0];
    const int*   xidx = (const int*)d_in[1];
    const float* E    = (const float*)d_in[2];
    const float* rhos = (const float*)d_in[3];
    const float* Cs   = (const float*)d_in[4];
    const float* Wq   = (const float*)d_in[5];
    const float* Wk   = (const float*)d_in[6];
    const float* Wv   = (const float*)d_in[7];
    const float* Wo   = (const float*)d_in[8];
    const float* Wpe  = (const float*)d_in[9];
    const float* lnkg = (const float*)d_in[10];
    const float* lnkb = (const float*)d_in[11];
    const float* lnqg = (const float*)d_in[12];
    const float* lnqb = (const float*)d_in[13];
    float* out = (float*)d_out;

    bf16 *wqh, *wql, *wkh, *wkl, *wvh, *wvl, *woh, *wol;
    bf16 *memh, *meml, *xhh, *xhl, *Qh, *Ql, *aoh, *aol;
    float *ek, *ev;
    cudaGetSymbolAddress((void**)&wqh, g_Wqh); cudaGetSymbolAddress((void**)&wql, g_Wql);
    cudaGetSymbolAddress((void**)&wkh, g_Wkh); cudaGetSymbolAddress((void**)&wkl, g_Wkl);
    cudaGetSymbolAddress((void**)&wvh, g_Wvh); cudaGetSymbolAddress((void**)&wvl, g_Wvl);
    cudaGetSymbolAddress((void**)&woh, g_Woh); cudaGetSymbolAddress((void**)&wol, g_Wol);
    cudaGetSymbolAddress((void**)&memh, g_memh); cudaGetSymbolAddress((void**)&meml, g_meml);
    cudaGetSymbolAddress((void**)&xhh, g_xhh); cudaGetSymbolAddress((void**)&xhl, g_xhl);
    cudaGetSymbolAddress((void**)&Qh, g_Qh); cudaGetSymbolAddress((void**)&Ql, g_Ql);
    cudaGetSymbolAddress((void**)&aoh, g_aoh); cudaGetSymbolAddress((void**)&aol, g_aol);
    cudaGetSymbolAddress((void**)&ek, g_ek); cudaGetSymbolAddress((void**)&ev, g_ev);

    const int gemm_smem = 8 * 128 * 80;            // 81920
    const int attn_smem = 6 * 64 * 144;            // 55296
    cudaFuncSetAttribute(gemm_bs<true>,  cudaFuncAttributeMaxDynamicSharedMemorySize, gemm_smem);
    cudaFuncSetAttribute(gemm_bs<false>, cudaFuncAttributeMaxDynamicSharedMemorySize, gemm_smem);
    cudaFuncSetAttribute(attn_kernel,    cudaFuncAttributeMaxDynamicSharedMemorySize, attn_smem);

    const int n2 = Dc * Dc / 2;
    split_w_kernel<<<(n2 + 255) / 256, 256>>>(Wq, wqh, wql, n2);
    split_w_kernel<<<(n2 + 255) / 256, 256>>>(Wk, wkh, wkl, n2);
    split_w_kernel<<<(n2 + 255) / 256, 256>>>(Wv, wvh, wvl, n2);
    split_w_kernel<<<(n2 + 255) / 256, 256>>>(Wo, woh, wol, n2);
    ln_rows_kernel<<<NSLOTc, 256>>>(E, lnkg, lnkb, memh, meml);
    ctab_kernel<<<(Sc * NSc + 255) / 256, 256>>>(rhos);

    gemm_bs<false><<<dim3(Dc / 128, NSLOTc / 128), 256, gemm_smem>>>(
        memh, meml, wkh, wkl, ek, nullptr, nullptr, NSLOTc, Dc, Dc);
    gemm_bs<false><<<dim3(Dc / 128, NSLOTc / 128), 256, gemm_smem>>>(
        memh, meml, wvh, wvl, ev, nullptr, nullptr, NSLOTc, Dc, Dc);
    gather_kernel<<<Bc * Sc, 256>>>(xidx, Wpe);

    gateq_ln_kernel<<<Bc * Lc, 256>>>(x_q, Cs, Wpe, lnqg, lnqb);
    gemm_bs<true><<<dim3(Dc / 128, BLc / 128), 256, gemm_smem>>>(
        xhh, xhl, wqh, wql, nullptr, Qh, Ql, BLc, Dc, Dc);

    attn_kernel<<<dim3(Lc / 64, Bc * Hc), 128, attn_smem>>>();

    gemm_bs<false><<<dim3(Dc / 128, BLc / 128), 256, gemm_smem>>>(
        aoh, aol, woh, wol, out, nullptr, nullptr, BLc, Dc, Dc);
}

// round 6
// speedup vs baseline: 2.0854x; 1.1317x over previous
#include <cuda_runtime.h>
#include <cuda_bf16.h>
#include <math.h>
#include <stdint.h>

#define Bc 2
#define Lc 2048
#define Sc 2048
#define Dc 1024
#define Hc 16
#define NSc 8
#define NSLOTc 512
#define HDc 64
#define BLc (Bc*Lc)
#define BSc (Bc*Sc)

typedef __nv_bfloat16 bf16;
typedef __nv_bfloat162 bf162;

// ---------------- scratch ----------------
__device__ __align__(16) bf16 g_Wqh[Dc*Dc], g_Wql[Dc*Dc];
__device__ __align__(16) bf16 g_Wkh[Dc*Dc], g_Wkl[Dc*Dc];
__device__ __align__(16) bf16 g_Wvh[Dc*Dc], g_Wvl[Dc*Dc];
__device__ __align__(16) bf16 g_Woh[Dc*Dc], g_Wol[Dc*Dc];
__device__ __align__(16) bf16 g_memh[NSLOTc*Dc], g_meml[NSLOTc*Dc];
__device__ __align__(16) float g_ek[NSLOTc*Dc], g_ev[NSLOTc*Dc];
__device__ __align__(16) float g_ctab[Sc*NSc];
__device__ __align__(16) bf16 g_Kh[(size_t)BSc*Dc], g_Kl[(size_t)BSc*Dc];
__device__ __align__(16) bf16 g_Vh[(size_t)BSc*Dc], g_Vl[(size_t)BSc*Dc];
__device__ __align__(16) bf16 g_xhh[(size_t)BLc*Dc], g_xhl[(size_t)BLc*Dc];
__device__ __align__(16) bf16 g_Qh[(size_t)BLc*Dc], g_Ql[(size_t)BLc*Dc];
__device__ __align__(16) bf16 g_aoh[(size_t)BLc*Dc], g_aol[(size_t)BLc*Dc];

// ---------------- helpers ----------------
__device__ __forceinline__ uint32_t smem_u32(const void* p) {
    return (uint32_t)__cvta_generic_to_shared(p);
}
__device__ __forceinline__ void ldsm_x4(uint32_t* r, uint32_t a) {
    asm volatile("ldmatrix.sync.aligned.m8n8.x4.shared.b16 {%0,%1,%2,%3}, [%4];"
                 : "=r"(r[0]), "=r"(r[1]), "=r"(r[2]), "=r"(r[3]) : "r"(a));
}
__device__ __forceinline__ void ldsm_x4t(uint32_t* r, uint32_t a) {
    asm volatile("ldmatrix.sync.aligned.m8n8.x4.trans.shared.b16 {%0,%1,%2,%3}, [%4];"
                 : "=r"(r[0]), "=r"(r[1]), "=r"(r[2]), "=r"(r[3]) : "r"(a));
}
__device__ __forceinline__ void mma_(float* c, const uint32_t* a, uint32_t b0, uint32_t b1) {
    asm volatile("mma.sync.aligned.m16n8k16.row.col.f32.bf16.bf16.f32 "
                 "{%0,%1,%2,%3},{%4,%5,%6,%7},{%8,%9},{%0,%1,%2,%3};"
                 : "+f"(c[0]), "+f"(c[1]), "+f"(c[2]), "+f"(c[3])
                 : "r"(a[0]), "r"(a[1]), "r"(a[2]), "r"(a[3]), "r"(b0), "r"(b1));
}
__device__ __forceinline__ void mma3(float* c, const uint32_t* ah, const uint32_t* al,
                                     uint32_t bh0, uint32_t bh1, uint32_t bl0, uint32_t bl1) {
    mma_(c, ah, bh0, bh1); mma_(c, ah, bl0, bl1); mma_(c, al, bh0, bh1);
}
__device__ __forceinline__ void cpa16(uint32_t s, const void* g) {
    asm volatile("cp.async.cg.shared.global [%0], [%1], 16;" :: "r"(s), "l"(g));
}
__device__ __forceinline__ void cpa_commit() { asm volatile("cp.async.commit_group;"); }
__device__ __forceinline__ void sst2(bf16* H, bf16* L, size_t o, float x, float y) {
    bf162 h = __floats2bfloat162_rn(x, y);
    bf162 l = __floats2bfloat162_rn(x - __bfloat162float(h.x), y - __bfloat162float(h.y));
    *(bf162*)(H + o) = h; *(bf162*)(L + o) = l;
}
__device__ __forceinline__ void splitpack(float x, float y, uint32_t& h, uint32_t& l) {
    bf162 hh = __floats2bfloat162_rn(x, y);
    bf162 ll = __floats2bfloat162_rn(x - __bfloat162float(hh.x), y - __bfloat162float(hh.y));
    h = *(uint32_t*)&hh; l = *(uint32_t*)&ll;
}
__device__ __forceinline__ float blockReduceSum(float v, float* red) {
    int tid = threadIdx.x, lane = tid & 31, w = tid >> 5;
#pragma unroll
    for (int o = 16; o; o >>= 1) v += __shfl_xor_sync(0xffffffffu, v, o);
    if (lane == 0) red[w] = v;
    __syncthreads();
    if (tid == 0) {
        float s = 0.f;
#pragma unroll
        for (int i = 0; i < 8; i++) s += red[i];
        red[0] = s;
    }
    __syncthreads();
    float r = red[0];
    __syncthreads();
    return r;
}
#define SWZ16(r, c) ((c) ^ ((r) & 7))

// ---------------- elementwise kernels ----------------
// All 4 weight splits in one launch. w==0 (Wq) pre-scaled by 1/sqrt(HD).
__global__ void split_w4_kernel(const float* __restrict__ Wq, const float* __restrict__ Wk,
                                const float* __restrict__ Wv, const float* __restrict__ Wo) {
    int w = blockIdx.y;
    int i = blockIdx.x * blockDim.x + threadIdx.x;
    const float* src = (w == 0) ? Wq : (w == 1) ? Wk : (w == 2) ? Wv : Wo;
    bf16* H = (w == 0) ? g_Wqh : (w == 1) ? g_Wkh : (w == 2) ? g_Wvh : g_Woh;
    bf16* L = (w == 0) ? g_Wql : (w == 1) ? g_Wkl : (w == 2) ? g_Wvl : g_Wol;
    float sc = (w == 0) ? 0.125f : 1.0f;
    float2 v = ((const float2*)src)[i];
    sst2(H, L, (size_t)i * 2, v.x * sc, v.y * sc);
}

__global__ void ln_rows_kernel(const float* __restrict__ X, const float* __restrict__ gw,
                               const float* __restrict__ bw,
                               bf16* __restrict__ Yh, bf16* __restrict__ Yl) {
    __shared__ float red[8];
    int r = blockIdx.x, tid = threadIdx.x;
    float4 x = *(const float4*)(X + (size_t)r * Dc + tid * 4);
    float mean = blockReduceSum(x.x + x.y + x.z + x.w, red) * (1.0f / Dc);
    float d0 = x.x - mean, d1 = x.y - mean, d2 = x.z - mean, d3 = x.w - mean;
    float var = blockReduceSum(d0*d0 + d1*d1 + d2*d2 + d3*d3, red) * (1.0f / Dc);
    float rs = rsqrtf(var + 1e-5f);
    float4 g4 = *(const float4*)(gw + tid * 4);
    float4 b4 = *(const float4*)(bw + tid * 4);
    size_t o = (size_t)r * Dc + tid * 4;
    sst2(Yh, Yl, o,     d0*rs*g4.x + b4.x, d1*rs*g4.y + b4.y);
    sst2(Yh, Yl, o + 2, d2*rs*g4.z + b4.z, d3*rs*g4.w + b4.w);
}

__global__ void ctab_kernel(const float* __restrict__ rhos) {
    int i = blockIdx.x * blockDim.x + threadIdx.x;
    if (i >= Sc * NSc) return;
    int s = i >> 3, m = i & 7;
    double age = (double)(Sc - 1 - s);
    g_ctab[i] = (float)exp(age * log((double)rhos[m]));
}

__global__ void gather_kernel(const int* __restrict__ xidx, const float* __restrict__ Wpe) {
    __shared__ float c[NSc];
    int bs = blockIdx.x, tid = threadIdx.x;
    int s = bs & (Sc - 1);
    int idx = xidx[bs];
    if (tid < NSc) c[tid] = g_ctab[s * NSc + tid];
    __syncthreads();
    float cc[NSc];
#pragma unroll
    for (int m = 0; m < NSc; m++) cc[m] = c[m];
    float4 ek4 = ((const float4*)(g_ek + (size_t)idx * Dc))[tid];
    float4 ev4 = ((const float4*)(g_ev + (size_t)idx * Dc))[tid];
    float kx[4] = {ek4.x, ek4.y, ek4.z, ek4.w};
    float vx[4] = {ev4.x, ev4.y, ev4.z, ev4.w};
#pragma unroll
    for (int e = 0; e < 4; e++) {
        const float* w = Wpe + (size_t)(tid * 4 + e) * NSc;
        float t = 0.f;
#pragma unroll
        for (int m = 0; m < NSc; m++) t += cc[m] * w[m];
        float g = t / (1.0f + __expf(-t));
        kx[e] *= g; vx[e] *= g;
    }
    size_t o = (size_t)bs * Dc + tid * 4;
    sst2(g_Kh, g_Kl, o, kx[0], kx[1]); sst2(g_Kh, g_Kl, o + 2, kx[2], kx[3]);
    sst2(g_Vh, g_Vl, o, vx[0], vx[1]); sst2(g_Vh, g_Vl, o + 2, vx[2], vx[3]);
}

__global__ void gateq_ln_kernel(const float* __restrict__ xq, const float* __restrict__ Cs,
                                const float* __restrict__ Wpe,
                                const float* __restrict__ gw, const float* __restrict__ bw) {
    __shared__ float red[8];
    __shared__ float c[NSc];
    int r = blockIdx.x, tid = threadIdx.x;
    if (tid < NSc) c[tid] = Cs[(size_t)r * NSc + tid];
    __syncthreads();
    float cc[NSc];
#pragma unroll
    for (int m = 0; m < NSc; m++) cc[m] = c[m];
    float4 x = *(const float4*)(xq + (size_t)r * Dc + tid * 4);
    float xv[4] = {x.x, x.y, x.z, x.w};
    float y[4];
#pragma unroll
    for (int e = 0; e < 4; e++) {
        const float* w = Wpe + (size_t)(tid * 4 + e) * NSc;
        float t = 0.f;
#pragma unroll
        for (int m = 0; m < NSc; m++) t += cc[m] * w[m];
        y[e] = xv[e] * (t / (1.0f + __expf(-t)));
    }
    float mean = blockReduceSum(y[0] + y[1] + y[2] + y[3], red) * (1.0f / Dc);
#pragma unroll
    for (int e = 0; e < 4; e++) y[e] -= mean;
    float var = blockReduceSum(y[0]*y[0] + y[1]*y[1] + y[2]*y[2] + y[3]*y[3], red) * (1.0f / Dc);
    float rs = rsqrtf(var + 1e-5f);
    float4 g4 = *(const float4*)(gw + tid * 4);
    float4 b4 = *(const float4*)(bw + tid * 4);
    size_t o = (size_t)r * Dc + tid * 4;
    sst2(g_xhh, g_xhl, o,     y[0]*rs*g4.x + b4.x, y[1]*rs*g4.y + b4.y);
    sst2(g_xhh, g_xhl, o + 2, y[2]*rs*g4.z + b4.z, y[3]*rs*g4.w + b4.w);
}

// ---------------- split-bf16 tensor-core GEMM: C[M,N] = A[M,K] * B[N,K]^T ----------------
template<bool SPLITOUT>
__global__ __launch_bounds__(256)
void gemm_bs(const bf16* __restrict__ Ah, const bf16* __restrict__ Al,
             const bf16* __restrict__ Bh, const bf16* __restrict__ Bl,
             float* __restrict__ C, bf16* __restrict__ Ch, bf16* __restrict__ Cl,
             int M, int N, int K) {
    extern __shared__ char smraw[];
    const int RS = 80, TB = 128 * RS;
    int tid = threadIdx.x, lane = tid & 31, warp = tid >> 5;
    int wm = (warp >> 1) * 32, wn = (warp & 1) * 64;
    int row0 = blockIdx.y * 128, col0 = blockIdx.x * 128;
    int r_ld = tid >> 1;
    const bf16* gp[4];
    gp[0] = Ah + (size_t)(row0 + r_ld) * K + (tid & 1) * 16;
    gp[1] = Al + (size_t)(row0 + r_ld) * K + (tid & 1) * 16;
    gp[2] = Bh + (size_t)(col0 + r_ld) * K + (tid & 1) * 16;
    gp[3] = Bl + (size_t)(col0 + r_ld) * K + (tid & 1) * 16;
    uint32_t sb = smem_u32(smraw);
    uint32_t st = (uint32_t)(r_ld * RS + (tid & 1) * 32);
    auto load = [&](int bf, int k0) {
#pragma unroll
        for (int o = 0; o < 4; o++) {
            uint32_t s = sb + (uint32_t)((bf * 4 + o) * TB) + st;
            cpa16(s, gp[o] + k0); cpa16(s + 16, gp[o] + k0 + 8);
        }
        cpa_commit();
    };
    float acc[2][8][4] = {};
    int mrow = lane & 15, mcb = (lane >> 4) * 16;
    const int KC = K / 32;
    load(0, 0);
    for (int kc = 0; kc < KC; kc++) {
        if (kc + 1 < KC) {
            load((kc + 1) & 1, (kc + 1) * 32);
            asm volatile("cp.async.wait_group 1;");
        } else {
            asm volatile("cp.async.wait_group 0;");
        }
        __syncthreads();
        uint32_t bo = sb + (uint32_t)((kc & 1) * 4 * TB);
#pragma unroll
        for (int ks = 0; ks < 2; ks++) {
            uint32_t ah[2][4], al[2][4];
#pragma unroll
            for (int i = 0; i < 2; i++) {
                uint32_t aa = bo + (uint32_t)((wm + i * 16 + mrow) * RS + ks * 32 + mcb);
                ldsm_x4(ah[i], aa); ldsm_x4(al[i], aa + TB);
            }
#pragma unroll
            for (int j2 = 0; j2 < 4; j2++) {
                uint32_t ba = bo + (uint32_t)(2 * TB + (wn + j2 * 16 + mrow) * RS + ks * 32 + mcb);
                uint32_t bh[4], bl[4];
                ldsm_x4(bh, ba); ldsm_x4(bl, ba + TB);
#pragma unroll
                for (int i = 0; i < 2; i++) {
                    mma3(acc[i][2 * j2],     ah[i], al[i], bh[0], bh[2], bl[0], bl[2]);
                    mma3(acc[i][2 * j2 + 1], ah[i], al[i], bh[1], bh[3], bl[1], bl[3]);
                }
            }
        }
        __syncthreads();
    }
    int r = lane >> 2, q = (lane & 3) * 2;
#pragma unroll
    for (int i = 0; i < 2; i++)
#pragma unroll
        for (int j = 0; j < 8; j++) {
            size_t g0 = (size_t)(row0 + wm + i * 16 + r) * N + col0 + wn + j * 8 + q;
            float* a = acc[i][j];
            if (SPLITOUT) {
                sst2(Ch, Cl, g0, a[0], a[1]);
                sst2(Ch, Cl, g0 + (size_t)8 * N, a[2], a[3]);
            } else {
                *(float2*)(C + g0) = make_float2(a[0], a[1]);
                *(float2*)(C + g0 + (size_t)8 * N) = make_float2(a[2], a[3]);
            }
        }
}

// ---------------- flash attention v2: 8 warps, 128-q tile, swizzled smem, 2-stage pipeline ----------------
// smem: Qh[0,16K) Ql[16K,32K) | stage0 {Kh,Kl,Vh,Vl}@32K+ (8KB each) | stage1 @64K+. Total 96KB.
__global__ __launch_bounds__(256, 2)
void attn_kernel() {
    extern __shared__ char smraw[];
    uint32_t sb = smem_u32(smraw);
    const uint32_t QL = 16384, KV0 = 32768, STG = 32768, ARR = 8192;
    int tid = threadIdx.x, lane = tid & 31, warp = tid >> 5;
    int b = blockIdx.y >> 4, h = blockIdx.y & 15;
    int q0 = blockIdx.x * 128;
    size_t qoff = ((size_t)(b * Lc + q0)) * Dc + h * HDc;
    size_t koff = ((size_t)b * Sc) * Dc + h * HDc;

    // Q tile load (rows 0..127)
    {
        int r = tid >> 1, cb = (tid & 1) * 4;
        const bf16* q_h = g_Qh + qoff + (size_t)r * Dc;
        const bf16* q_l = g_Ql + qoff + (size_t)r * Dc;
#pragma unroll
        for (int j = 0; j < 4; j++) {
            int c = cb + j;
            uint32_t d = (uint32_t)(r * 128 + SWZ16(r, c) * 16);
            cpa16(sb + d, q_h + c * 8);
            cpa16(sb + QL + d, q_l + c * 8);
        }
        cpa_commit();
    }
    // KV stage loader (rows 0..63)
    int kr = tid >> 2, kcb = (tid & 3) * 2;
    const bf16* gsrc[4] = {g_Kh + koff + (size_t)kr * Dc, g_Kl + koff + (size_t)kr * Dc,
                           g_Vh + koff + (size_t)kr * Dc, g_Vl + koff + (size_t)kr * Dc};
    uint32_t kdst[2];
#pragma unroll
    for (int j = 0; j < 2; j++)
        kdst[j] = (uint32_t)(kr * 128 + SWZ16(kr, kcb + j) * 16);
    auto loadKV = [&](int stage, int sc) {
        size_t go = (size_t)sc * 64 * Dc;
        uint32_t sbase = sb + KV0 + (uint32_t)stage * STG;
#pragma unroll
        for (int o = 0; o < 4; o++)
#pragma unroll
            for (int j = 0; j < 2; j++)
                cpa16(sbase + (uint32_t)(o * ARR) + kdst[j], gsrc[o] + go + (kcb + j) * 8);
        cpa_commit();
    };
    loadKV(0, 0);
    asm volatile("cp.async.wait_group 1;");   // Q complete, stage0 may be in flight
    __syncthreads();

    // persistent Q fragments (warp rows = warp*16 .. +15)
    int mrow = lane & 15, mc = lane >> 4;
    uint32_t qh[4][4], ql[4][4];
#pragma unroll
    for (int ks = 0; ks < 4; ks++) {
        int r = warp * 16 + mrow;
        uint32_t d = (uint32_t)(r * 128 + SWZ16(r, ks * 2 + mc) * 16);
        ldsm_x4(qh[ks], sb + d);
        ldsm_x4(ql[ks], sb + QL + d);
    }

    float Oa[8][4] = {};
    float mr[2] = {-1e30f, -1e30f}, lrr[2] = {0.f, 0.f};
    const int NC = Sc / 64;
    for (int sc = 0; sc < NC; sc++) {
        if (sc + 1 < NC) {
            loadKV((sc + 1) & 1, sc + 1);
            asm volatile("cp.async.wait_group 1;");
        } else {
            asm volatile("cp.async.wait_group 0;");
        }
        __syncthreads();
        uint32_t stg = sb + KV0 + (uint32_t)((sc & 1) * STG);
        // S = Q K^T (scale pre-folded into Wq)
        float Sa[8][4] = {};
#pragma unroll
        for (int ks = 0; ks < 4; ks++)
#pragma unroll
            for (int j2 = 0; j2 < 4; j2++) {
                int r = j2 * 16 + mrow;
                uint32_t d = (uint32_t)(r * 128 + SWZ16(r, ks * 2 + mc) * 16);
                uint32_t bh[4], bl[4];
                ldsm_x4(bh, stg + d);
                ldsm_x4(bl, stg + ARR + d);
                mma3(Sa[2 * j2],     qh[ks], ql[ks], bh[0], bh[2], bl[0], bl[2]);
                mma3(Sa[2 * j2 + 1], qh[ks], ql[ks], bh[1], bh[3], bl[1], bl[3]);
            }
        // online softmax (rows lane>>2 and +8)
        float mx[2] = {-1e30f, -1e30f};
#pragma unroll
        for (int j = 0; j < 8; j++) {
            mx[0] = fmaxf(mx[0], fmaxf(Sa[j][0], Sa[j][1]));
            mx[1] = fmaxf(mx[1], fmaxf(Sa[j][2], Sa[j][3]));
        }
        float al2[2];
#pragma unroll
        for (int t = 0; t < 2; t++) {
            mx[t] = fmaxf(mx[t], __shfl_xor_sync(0xffffffffu, mx[t], 1));
            mx[t] = fmaxf(mx[t], __shfl_xor_sync(0xffffffffu, mx[t], 2));
            float nm = fmaxf(mr[t], mx[t]);
            al2[t] = __expf(mr[t] - nm);
            mr[t] = nm;
        }
        float rs[2] = {0.f, 0.f};
#pragma unroll
        for (int j = 0; j < 8; j++) {
            Sa[j][0] = __expf(Sa[j][0] - mr[0]); Sa[j][1] = __expf(Sa[j][1] - mr[0]);
            Sa[j][2] = __expf(Sa[j][2] - mr[1]); Sa[j][3] = __expf(Sa[j][3] - mr[1]);
            rs[0] += Sa[j][0] + Sa[j][1]; rs[1] += Sa[j][2] + Sa[j][3];
            Oa[j][0] *= al2[0]; Oa[j][1] *= al2[0];
            Oa[j][2] *= al2[1]; Oa[j][3] *= al2[1];
        }
#pragma unroll
        for (int t = 0; t < 2; t++) {
            rs[t] += __shfl_xor_sync(0xffffffffu, rs[t], 1);
            rs[t] += __shfl_xor_sync(0xffffffffu, rs[t], 2);
            lrr[t] = lrr[t] * al2[t] + rs[t];
        }
        // O += P V (P split in registers; C-frag == A-frag layout)
#pragma unroll
        for (int kk = 0; kk < 4; kk++) {
            uint32_t ph[4], pl[4];
            splitpack(Sa[2 * kk][0],     Sa[2 * kk][1],     ph[0], pl[0]);
            splitpack(Sa[2 * kk][2],     Sa[2 * kk][3],     ph[1], pl[1]);
            splitpack(Sa[2 * kk + 1][0], Sa[2 * kk + 1][1], ph[2], pl[2]);
            splitpack(Sa[2 * kk + 1][2], Sa[2 * kk + 1][3], ph[3], pl[3]);
#pragma unroll
            for (int j2 = 0; j2 < 4; j2++) {
                int r = kk * 16 + mrow;
                uint32_t d = (uint32_t)(r * 128 + SWZ16(r, j2 * 2 + mc) * 16);
                uint32_t vh[4], vl[4];
                ldsm_x4t(vh, stg + 2 * ARR + d);
                ldsm_x4t(vl, stg + 3 * ARR + d);
                mma3(Oa[2 * j2],     ph, pl, vh[0], vh[1], vl[0], vl[1]);
                mma3(Oa[2 * j2 + 1], ph, pl, vh[2], vh[3], vl[2], vl[3]);
            }
        }
        __syncthreads();
    }
    float inv0 = 1.f / lrr[0], inv1 = 1.f / lrr[1];
    int r = lane >> 2, q = (lane & 3) * 2;
    size_t o0 = qoff + (size_t)(warp * 16 + r) * Dc;
#pragma unroll
    for (int j = 0; j < 8; j++) {
        sst2(g_aoh, g_aol, o0 + j * 8 + q, Oa[j][0] * inv0, Oa[j][1] * inv0);
        sst2(g_aoh, g_aol, o0 + (size_t)8 * Dc + j * 8 + q, Oa[j][2] * inv1, Oa[j][3] * inv1);
    }
}

// ---------------- launch ----------------
extern "C" void kernel_launch(void* const* d_in, const int* in_sizes, int n_in,
                              void* d_out, int out_size) {
    const float* x_q  = (const float*)d_in[0];
    const int*   xidx = (const int*)d_in[1];
    const float* E    = (const float*)d_in[2];
    const float* rhos = (const float*)d_in[3];
    const float* Cs   = (const float*)d_in[4];
    const float* Wq   = (const float*)d_in[5];
    const float* Wk   = (const float*)d_in[6];
    const float* Wv   = (const float*)d_in[7];
    const float* Wo   = (const float*)d_in[8];
    const float* Wpe  = (const float*)d_in[9];
    const float* lnkg = (const float*)d_in[10];
    const float* lnkb = (const float*)d_in[11];
    const float* lnqg = (const float*)d_in[12];
    const float* lnqb = (const float*)d_in[13];
    float* out = (float*)d_out;

    bf16 *wqh, *wql, *wkh, *wkl, *wvh, *wvl, *woh, *wol;
    bf16 *memh, *meml, *xhh, *xhl, *Qh, *Ql, *aoh, *aol;
    float *ek, *ev;
    cudaGetSymbolAddress((void**)&wqh, g_Wqh); cudaGetSymbolAddress((void**)&wql, g_Wql);
    cudaGetSymbolAddress((void**)&wkh, g_Wkh); cudaGetSymbolAddress((void**)&wkl, g_Wkl);
    cudaGetSymbolAddress((void**)&wvh, g_Wvh); cudaGetSymbolAddress((void**)&wvl, g_Wvl);
    cudaGetSymbolAddress((void**)&woh, g_Woh); cudaGetSymbolAddress((void**)&wol, g_Wol);
    cudaGetSymbolAddress((void**)&memh, g_memh); cudaGetSymbolAddress((void**)&meml, g_meml);
    cudaGetSymbolAddress((void**)&xhh, g_xhh); cudaGetSymbolAddress((void**)&xhl, g_xhl);
    cudaGetSymbolAddress((void**)&Qh, g_Qh); cudaGetSymbolAddress((void**)&Ql, g_Ql);
    cudaGetSymbolAddress((void**)&aoh, g_aoh); cudaGetSymbolAddress((void**)&aol, g_aol);
    cudaGetSymbolAddress((void**)&ek, g_ek); cudaGetSymbolAddress((void**)&ev, g_ev);

    const int gemm_smem = 8 * 128 * 80;   // 81920
    const int attn_smem = 98304;          // 96KB: Q 32KB + 2-stage KV 64KB
    cudaFuncSetAttribute(gemm_bs<true>,  cudaFuncAttributeMaxDynamicSharedMemorySize, gemm_smem);
    cudaFuncSetAttribute(gemm_bs<false>, cudaFuncAttributeMaxDynamicSharedMemorySize, gemm_smem);
    cudaFuncSetAttribute(attn_kernel,    cudaFuncAttributeMaxDynamicSharedMemorySize, attn_smem);

    const int n2 = Dc * Dc / 2;
    split_w4_kernel<<<dim3(n2 / 256, 4), 256>>>(Wq, Wk, Wv, Wo);
    ln_rows_kernel<<<NSLOTc, 256>>>(E, lnkg, lnkb, memh, meml);
    ctab_kernel<<<(Sc * NSc + 255) / 256, 256>>>(rhos);

    gemm_bs<false><<<dim3(Dc / 128, NSLOTc / 128), 256, gemm_smem>>>(
        memh, meml, wkh, wkl, ek, nullptr, nullptr, NSLOTc, Dc, Dc);
    gemm_bs<false><<<dim3(Dc / 128, NSLOTc / 128), 256, gemm_smem>>>(
        memh, meml, wvh, wvl, ev, nullptr, nullptr, NSLOTc, Dc, Dc);
    gather_kernel<<<Bc * Sc, 256>>>(xidx, Wpe);

    gateq_ln_kernel<<<Bc * Lc, 256>>>(x_q, Cs, Wpe, lnqg, lnqb);
    gemm_bs<true><<<dim3(Dc / 128, BLc / 128), 256, gemm_smem>>>(
        xhh, xhl, wqh, wql, nullptr, Qh, Ql, BLc, Dc, Dc);

    attn_kernel<<<dim3(Lc / 128, Bc * Hc), 256, attn_smem>>>();

    gemm_bs<false><<<dim3(Dc / 128, BLc / 128), 256, gemm_smem>>>(
        aoh, aol, woh, wol, out, nullptr, nullptr, BLc, Dc, Dc);
}

// round 8
// speedup vs baseline: 2.4031x; 1.1523x over previous
#include <cuda_runtime.h>
#include <cuda_bf16.h>
#include <math.h>
#include <stdint.h>

#define Bc 2
#define Lc 2048
#define Sc 2048
#define Dc 1024
#define Hc 16
#define NSc 8
#define NSLOTc 512
#define HDc 64
#define BLc (Bc*Lc)
#define BSc (Bc*Sc)

typedef __nv_bfloat16 bf16;
typedef __nv_bfloat162 bf162;

// ---------------- scratch ----------------
__device__ __align__(16) bf16 g_Wqh[Dc*Dc], g_Wql[Dc*Dc];
__device__ __align__(16) bf16 g_Wkh[Dc*Dc], g_Wkl[Dc*Dc];
__device__ __align__(16) bf16 g_Wvh[Dc*Dc], g_Wvl[Dc*Dc];
__device__ __align__(16) bf16 g_Woh[Dc*Dc], g_Wol[Dc*Dc];
__device__ __align__(16) bf16 g_memh[NSLOTc*Dc], g_meml[NSLOTc*Dc];
__device__ __align__(16) float g_ek[NSLOTc*Dc], g_ev[NSLOTc*Dc];
__device__ __align__(16) float g_ctab[Sc*NSc];
__device__ __align__(16) bf16 g_Kh[(size_t)BSc*Dc], g_Kl[(size_t)BSc*Dc];
__device__ __align__(16) bf16 g_Vh[(size_t)BSc*Dc], g_Vl[(size_t)BSc*Dc];
__device__ __align__(16) bf16 g_xhh[(size_t)BLc*Dc], g_xhl[(size_t)BLc*Dc];
__device__ __align__(16) bf16 g_Qh[(size_t)BLc*Dc], g_Ql[(size_t)BLc*Dc];
__device__ __align__(16) bf16 g_aoh[(size_t)BLc*Dc], g_aol[(size_t)BLc*Dc];

// ---------------- helpers ----------------
__device__ __forceinline__ uint32_t smem_u32(const void* p) {
    return (uint32_t)__cvta_generic_to_shared(p);
}
__device__ __forceinline__ void ldsm_x4(uint32_t* r, uint32_t a) {
    asm volatile("ldmatrix.sync.aligned.m8n8.x4.shared.b16 {%0,%1,%2,%3}, [%4];"
                 : "=r"(r[0]), "=r"(r[1]), "=r"(r[2]), "=r"(r[3]) : "r"(a));
}
__device__ __forceinline__ void ldsm_x4t(uint32_t* r, uint32_t a) {
    asm volatile("ldmatrix.sync.aligned.m8n8.x4.trans.shared.b16 {%0,%1,%2,%3}, [%4];"
                 : "=r"(r[0]), "=r"(r[1]), "=r"(r[2]), "=r"(r[3]) : "r"(a));
}
__device__ __forceinline__ void mma_(float* c, const uint32_t* a, uint32_t b0, uint32_t b1) {
    asm volatile("mma.sync.aligned.m16n8k16.row.col.f32.bf16.bf16.f32 "
                 "{%0,%1,%2,%3},{%4,%5,%6,%7},{%8,%9},{%0,%1,%2,%3};"
                 : "+f"(c[0]), "+f"(c[1]), "+f"(c[2]), "+f"(c[3])
                 : "r"(a[0]), "r"(a[1]), "r"(a[2]), "r"(a[3]), "r"(b0), "r"(b1));
}
__device__ __forceinline__ void mma3(float* c, const uint32_t* ah, const uint32_t* al,
                                     uint32_t bh0, uint32_t bh1, uint32_t bl0, uint32_t bl1) {
    mma_(c, ah, bh0, bh1); mma_(c, ah, bl0, bl1); mma_(c, al, bh0, bh1);
}
__device__ __forceinline__ void cpa16(uint32_t s, const void* g) {
    asm volatile("cp.async.cg.shared.global [%0], [%1], 16;" :: "r"(s), "l"(g));
}
__device__ __forceinline__ void cpa_commit() { asm volatile("cp.async.commit_group;"); }
__device__ __forceinline__ void sst2(bf16* H, bf16* L, size_t o, float x, float y) {
    bf162 h = __floats2bfloat162_rn(x, y);
    bf162 l = __floats2bfloat162_rn(x - __bfloat162float(h.x), y - __bfloat162float(h.y));
    *(bf162*)(H + o) = h; *(bf162*)(L + o) = l;
}
__device__ __forceinline__ uint32_t packhi(float x, float y) {
    bf162 h = __floats2bfloat162_rn(x, y);
    return *(uint32_t*)&h;
}
__device__ __forceinline__ float blockReduceSum(float v, float* red) {
    int tid = threadIdx.x, lane = tid & 31, w = tid >> 5;
#pragma unroll
    for (int o = 16; o; o >>= 1) v += __shfl_xor_sync(0xffffffffu, v, o);
    if (lane == 0) red[w] = v;
    __syncthreads();
    if (tid == 0) {
        float s = 0.f;
#pragma unroll
        for (int i = 0; i < 8; i++) s += red[i];
        red[0] = s;
    }
    __syncthreads();
    float r = red[0];
    __syncthreads();
    return r;
}
#define SWZ16(r, c) ((c) ^ ((r) & 7))

// ---------------- elementwise kernels ----------------
// w==0 (Wq) pre-scaled by log2(e)/sqrt(HD) so softmax runs in base-2.
__global__ void split_w4_kernel(const float* __restrict__ Wq, const float* __restrict__ Wk,
                                const float* __restrict__ Wv, const float* __restrict__ Wo) {
    int w = blockIdx.y;
    int i = blockIdx.x * blockDim.x + threadIdx.x;
    const float* src = (w == 0) ? Wq : (w == 1) ? Wk : (w == 2) ? Wv : Wo;
    bf16* H = (w == 0) ? g_Wqh : (w == 1) ? g_Wkh : (w == 2) ? g_Wvh : g_Woh;
    bf16* L = (w == 0) ? g_Wql : (w == 1) ? g_Wkl : (w == 2) ? g_Wvl : g_Wol;
    float sc = (w == 0) ? 0.18033688011112042f : 1.0f;  // 0.125 * log2(e)
    float2 v = ((const float2*)src)[i];
    sst2(H, L, (size_t)i * 2, v.x * sc, v.y * sc);
}

__global__ void ln_rows_kernel(const float* __restrict__ X, const float* __restrict__ gw,
                               const float* __restrict__ bw,
                               bf16* __restrict__ Yh, bf16* __restrict__ Yl) {
    __shared__ float red[8];
    int r = blockIdx.x, tid = threadIdx.x;
    float4 x = *(const float4*)(X + (size_t)r * Dc + tid * 4);
    float mean = blockReduceSum(x.x + x.y + x.z + x.w, red) * (1.0f / Dc);
    float d0 = x.x - mean, d1 = x.y - mean, d2 = x.z - mean, d3 = x.w - mean;
    float var = blockReduceSum(d0*d0 + d1*d1 + d2*d2 + d3*d3, red) * (1.0f / Dc);
    float rs = rsqrtf(var + 1e-5f);
    float4 g4 = *(const float4*)(gw + tid * 4);
    float4 b4 = *(const float4*)(bw + tid * 4);
    size_t o = (size_t)r * Dc + tid * 4;
    sst2(Yh, Yl, o,     d0*rs*g4.x + b4.x, d1*rs*g4.y + b4.y);
    sst2(Yh, Yl, o + 2, d2*rs*g4.z + b4.z, d3*rs*g4.w + b4.w);
}

__global__ void ctab_kernel(const float* __restrict__ rhos) {
    int i = blockIdx.x * blockDim.x + threadIdx.x;
    if (i >= Sc * NSc) return;
    int s = i >> 3, m = i & 7;
    double age = (double)(Sc - 1 - s);
    g_ctab[i] = (float)exp(age * log((double)rhos[m]));
}

__global__ void gather_kernel(const int* __restrict__ xidx, const float* __restrict__ Wpe) {
    __shared__ float c[NSc];
    int bs = blockIdx.x, tid = threadIdx.x;
    int s = bs & (Sc - 1);
    int idx = xidx[bs];
    if (tid < NSc) c[tid] = g_ctab[s * NSc + tid];
    __syncthreads();
    float cc[NSc];
#pragma unroll
    for (int m = 0; m < NSc; m++) cc[m] = c[m];
    float4 ek4 = ((const float4*)(g_ek + (size_t)idx * Dc))[tid];
    float4 ev4 = ((const float4*)(g_ev + (size_t)idx * Dc))[tid];
    float kx[4] = {ek4.x, ek4.y, ek4.z, ek4.w};
    float vx[4] = {ev4.x, ev4.y, ev4.z, ev4.w};
#pragma unroll
    for (int e = 0; e < 4; e++) {
        const float* w = Wpe + (size_t)(tid * 4 + e) * NSc;
        float t = 0.f;
#pragma unroll
        for (int m = 0; m < NSc; m++) t += cc[m] * w[m];
        float g = t / (1.0f + __expf(-t));
        kx[e] *= g; vx[e] *= g;
    }
    size_t o = (size_t)bs * Dc + tid * 4;
    sst2(g_Kh, g_Kl, o, kx[0], kx[1]); sst2(g_Kh, g_Kl, o + 2, kx[2], kx[3]);
    sst2(g_Vh, g_Vl, o, vx[0], vx[1]); sst2(g_Vh, g_Vl, o + 2, vx[2], vx[3]);
}

__global__ void gateq_ln_kernel(const float* __restrict__ xq, const float* __restrict__ Cs,
                                const float* __restrict__ Wpe,
                                const float* __restrict__ gw, const float* __restrict__ bw) {
    __shared__ float red[8];
    __shared__ float c[NSc];
    int r = blockIdx.x, tid = threadIdx.x;
    if (tid < NSc) c[tid] = Cs[(size_t)r * NSc + tid];
    __syncthreads();
    float cc[NSc];
#pragma unroll
    for (int m = 0; m < NSc; m++) cc[m] = c[m];
    float4 x = *(const float4*)(xq + (size_t)r * Dc + tid * 4);
    float xv[4] = {x.x, x.y, x.z, x.w};
    float y[4];
#pragma unroll
    for (int e = 0; e < 4; e++) {
        const float* w = Wpe + (size_t)(tid * 4 + e) * NSc;
        float t = 0.f;
#pragma unroll
        for (int m = 0; m < NSc; m++) t += cc[m] * w[m];
        y[e] = xv[e] * (t / (1.0f + __expf(-t)));
    }
    float mean = blockReduceSum(y[0] + y[1] + y[2] + y[3], red) * (1.0f / Dc);
#pragma unroll
    for (int e = 0; e < 4; e++) y[e] -= mean;
    float var = blockReduceSum(y[0]*y[0] + y[1]*y[1] + y[2]*y[2] + y[3]*y[3], red) * (1.0f / Dc);
    float rs = rsqrtf(var + 1e-5f);
    float4 g4 = *(const float4*)(gw + tid * 4);
    float4 b4 = *(const float4*)(bw + tid * 4);
    size_t o = (size_t)r * Dc + tid * 4;
    sst2(g_xhh, g_xhl, o,     y[0]*rs*g4.x + b4.x, y[1]*rs*g4.y + b4.y);
    sst2(g_xhh, g_xhl, o + 2, y[2]*rs*g4.z + b4.z, y[3]*rs*g4.w + b4.w);
}

// ---------------- split-bf16 mma.sync GEMM core: C[tile] = A * B^T ----------------
// 128x128 tile, BK=32, 256 threads (8 warps 4m x 2n), double-buffered cp.async.
template<bool SPLITOUT>
__device__ __forceinline__
void gemm_core(const bf16* __restrict__ Ah, const bf16* __restrict__ Al,
               const bf16* __restrict__ Bh, const bf16* __restrict__ Bl,
               float* __restrict__ C, bf16* __restrict__ Ch, bf16* __restrict__ Cl,
               int N, int K, int row0, int col0, char* smraw) {
    const int RS = 80, TB = 128 * RS;
    int tid = threadIdx.x, lane = tid & 31, warp = tid >> 5;
    int wm = (warp >> 1) * 32, wn = (warp & 1) * 64;
    int r_ld = tid >> 1;
    const bf16* gp[4];
    gp[0] = Ah + (size_t)(row0 + r_ld) * K + (tid & 1) * 16;
    gp[1] = Al + (size_t)(row0 + r_ld) * K + (tid & 1) * 16;
    gp[2] = Bh + (size_t)(col0 + r_ld) * K + (tid & 1) * 16;
    gp[3] = Bl + (size_t)(col0 + r_ld) * K + (tid & 1) * 16;
    uint32_t sb = smem_u32(smraw);
    uint32_t st = (uint32_t)(r_ld * RS + (tid & 1) * 32);
    auto load = [&](int bf, int k0) {
#pragma unroll
        for (int o = 0; o < 4; o++) {
            uint32_t s = sb + (uint32_t)((bf * 4 + o) * TB) + st;
            cpa16(s, gp[o] + k0); cpa16(s + 16, gp[o] + k0 + 8);
        }
        cpa_commit();
    };
    float acc[2][8][4] = {};
    int mrow = lane & 15, mcb = (lane >> 4) * 16;
    const int KC = K / 32;
    load(0, 0);
    for (int kc = 0; kc < KC; kc++) {
        if (kc + 1 < KC) {
            load((kc + 1) & 1, (kc + 1) * 32);
            asm volatile("cp.async.wait_group 1;");
        } else {
            asm volatile("cp.async.wait_group 0;");
        }
        __syncthreads();
        uint32_t bo = sb + (uint32_t)((kc & 1) * 4 * TB);
#pragma unroll
        for (int ks = 0; ks < 2; ks++) {
            uint32_t ah[2][4], al[2][4];
#pragma unroll
            for (int i = 0; i < 2; i++) {
                uint32_t aa = bo + (uint32_t)((wm + i * 16 + mrow) * RS + ks * 32 + mcb);
                ldsm_x4(ah[i], aa); ldsm_x4(al[i], aa + TB);
            }
#pragma unroll
            for (int j2 = 0; j2 < 4; j2++) {
                uint32_t ba = bo + (uint32_t)(2 * TB + (wn + j2 * 16 + mrow) * RS + ks * 32 + mcb);
                uint32_t bh[4], bl[4];
                ldsm_x4(bh, ba); ldsm_x4(bl, ba + TB);
#pragma unroll
                for (int i = 0; i < 2; i++) {
                    mma3(acc[i][2 * j2],     ah[i], al[i], bh[0], bh[2], bl[0], bl[2]);
                    mma3(acc[i][2 * j2 + 1], ah[i], al[i], bh[1], bh[3], bl[1], bl[3]);
                }
            }
        }
        __syncthreads();
    }
    int r = lane >> 2, q = (lane & 3) * 2;
#pragma unroll
    for (int i = 0; i < 2; i++)
#pragma unroll
        for (int j = 0; j < 8; j++) {
            size_t g0 = (size_t)(row0 + wm + i * 16 + r) * N + col0 + wn + j * 8 + q;
            float* a = acc[i][j];
            if (SPLITOUT) {
                sst2(Ch, Cl, g0, a[0], a[1]);
                sst2(Ch, Cl, g0 + (size_t)8 * N, a[2], a[3]);
            } else {
                *(float2*)(C + g0) = make_float2(a[0], a[1]);
                *(float2*)(C + g0 + (size_t)8 * N) = make_float2(a[2], a[3]);
            }
        }
}

template<bool SPLITOUT>
__global__ __launch_bounds__(256)
void gemm_bs(const bf16* __restrict__ Ah, const bf16* __restrict__ Al,
             const bf16* __restrict__ Bh, const bf16* __restrict__ Bl,
             float* __restrict__ C, bf16* __restrict__ Ch, bf16* __restrict__ Cl,
             int M, int N, int K) {
    extern __shared__ char smraw[];
    gemm_core<SPLITOUT>(Ah, Al, Bh, Bl, C, Ch, Cl, N, K,
                        blockIdx.y * 128, blockIdx.x * 128, smraw);
}

// Fused K+V projection: blockIdx.x 0..7 -> Ek tile cols, 8..15 -> Ev tile cols.
__global__ __launch_bounds__(256)
void gemm_kv() {
    extern __shared__ char smraw[];
    int bx = blockIdx.x;
    if (bx < 8)
        gemm_core<false>(g_memh, g_meml, g_Wkh, g_Wkl, g_ek, nullptr, nullptr,
                         Dc, Dc, blockIdx.y * 128, bx * 128, smraw);
    else
        gemm_core<false>(g_memh, g_meml, g_Wvh, g_Wvl, g_ev, nullptr, nullptr,
                         Dc, Dc, blockIdx.y * 128, (bx - 8) * 128, smraw);
}

// ---------------- flash attention: 8 warps, 128-q tile, 2-stage pipeline, base-2 softmax ----------------
__global__ __launch_bounds__(256, 2)
void attn_kernel() {
    extern __shared__ char smraw[];
    uint32_t sb = smem_u32(smraw);
    const uint32_t QL = 16384, KV0 = 32768, STG = 32768, ARR = 8192;
    int tid = threadIdx.x, lane = tid & 31, warp = tid >> 5;
    int b = blockIdx.y >> 4, h = blockIdx.y & 15;
    int q0 = blockIdx.x * 128;
    size_t qoff = ((size_t)(b * Lc + q0)) * Dc + h * HDc;
    size_t koff = ((size_t)b * Sc) * Dc + h * HDc;
    {
        int r = tid >> 1, cb = (tid & 1) * 4;
        const bf16* q_h = g_Qh + qoff + (size_t)r * Dc;
        const bf16* q_l = g_Ql + qoff + (size_t)r * Dc;
#pragma unroll
        for (int j = 0; j < 4; j++) {
            int c = cb + j;
            uint32_t d = (uint32_t)(r * 128 + SWZ16(r, c) * 16);
            cpa16(sb + d, q_h + c * 8);
            cpa16(sb + QL + d, q_l + c * 8);
        }
        cpa_commit();
    }
    int kr = tid >> 2, kcb = (tid & 3) * 2;
    const bf16* gsrc[4] = {g_Kh + koff + (size_t)kr * Dc, g_Kl + koff + (size_t)kr * Dc,
                           g_Vh + koff + (size_t)kr * Dc, g_Vl + koff + (size_t)kr * Dc};
    uint32_t kdst[2];
#pragma unroll
    for (int j = 0; j < 2; j++)
        kdst[j] = (uint32_t)(kr * 128 + SWZ16(kr, kcb + j) * 16);
    auto loadKV = [&](int stage, int sc) {
        size_t go = (size_t)sc * 64 * Dc;
        uint32_t sbase = sb + KV0 + (uint32_t)stage * STG;
#pragma unroll
        for (int o = 0; o < 4; o++)
#pragma unroll
            for (int j = 0; j < 2; j++)
                cpa16(sbase + (uint32_t)(o * ARR) + kdst[j], gsrc[o] + go + (kcb + j) * 8);
        cpa_commit();
    };
    loadKV(0, 0);
    asm volatile("cp.async.wait_group 1;");
    __syncthreads();
    int mrow = lane & 15, mc = lane >> 4;
    uint32_t qh[4][4], ql[4][4];
#pragma unroll
    for (int ks = 0; ks < 4; ks++) {
        int r = warp * 16 + mrow;
        uint32_t d = (uint32_t)(r * 128 + SWZ16(r, ks * 2 + mc) * 16);
        ldsm_x4(qh[ks], sb + d);
        ldsm_x4(ql[ks], sb + QL + d);
    }
    float Oa[8][4] = {};
    float mr[2] = {-1e30f, -1e30f}, lrr[2] = {0.f, 0.f};
    const int NC = Sc / 64;
    for (int sc = 0; sc < NC; sc++) {
        if (sc + 1 < NC) {
            loadKV((sc + 1) & 1, sc + 1);
            asm volatile("cp.async.wait_group 1;");
        } else {
            asm volatile("cp.async.wait_group 0;");
        }
        __syncthreads();
        uint32_t stg = sb + KV0 + (uint32_t)((sc & 1) * STG);
        // S = Q K^T in base-2 log units (log2e/8 folded into Wq)
        float Sa[8][4] = {};
#pragma unroll
        for (int ks = 0; ks < 4; ks++)
#pragma unroll
            for (int j2 = 0; j2 < 4; j2++) {
                int r = j2 * 16 + mrow;
                uint32_t d = (uint32_t)(r * 128 + SWZ16(r, ks * 2 + mc) * 16);
                uint32_t bh[4], bl[4];
                ldsm_x4(bh, stg + d);
                ldsm_x4(bl, stg + ARR + d);
                mma3(Sa[2 * j2],     qh[ks], ql[ks], bh[0], bh[2], bl[0], bl[2]);
                mma3(Sa[2 * j2 + 1], qh[ks], ql[ks], bh[1], bh[3], bl[1], bl[3]);
            }
        // online softmax (base 2)
        float mx[2] = {-1e30f, -1e30f};
#pragma unroll
        for (int j = 0; j < 8; j++) {
            mx[0] = fmaxf(mx[0], fmaxf(Sa[j][0], Sa[j][1]));
            mx[1] = fmaxf(mx[1], fmaxf(Sa[j][2], Sa[j][3]));
        }
        float al2[2];
#pragma unroll
        for (int t = 0; t < 2; t++) {
            mx[t] = fmaxf(mx[t], __shfl_xor_sync(0xffffffffu, mx[t], 1));
            mx[t] = fmaxf(mx[t], __shfl_xor_sync(0xffffffffu, mx[t], 2));
            float nm = fmaxf(mr[t], mx[t]);
            al2[t] = exp2f(mr[t] - nm);
            mr[t] = nm;
        }
        float rs[2] = {0.f, 0.f};
#pragma unroll
        for (int j = 0; j < 8; j++) {
            Sa[j][0] = exp2f(Sa[j][0] - mr[0]); Sa[j][1] = exp2f(Sa[j][1] - mr[0]);
            Sa[j][2] = exp2f(Sa[j][2] - mr[1]); Sa[j][3] = exp2f(Sa[j][3] - mr[1]);
            rs[0] += Sa[j][0] + Sa[j][1]; rs[1] += Sa[j][2] + Sa[j][3];
            Oa[j][0] *= al2[0]; Oa[j][1] *= al2[0];
            Oa[j][2] *= al2[1]; Oa[j][3] *= al2[1];
        }
#pragma unroll
        for (int t = 0; t < 2; t++) {
            rs[t] += __shfl_xor_sync(0xffffffffu, rs[t], 1);
            rs[t] += __shfl_xor_sync(0xffffffffu, rs[t], 2);
            lrr[t] = lrr[t] * al2[t] + rs[t];
        }
        // pack P (hi only) first — Sa dies here, lowering peak register pressure
        uint32_t php[4][4];
#pragma unroll
        for (int kk = 0; kk < 4; kk++) {
            php[kk][0] = packhi(Sa[2 * kk][0],     Sa[2 * kk][1]);
            php[kk][1] = packhi(Sa[2 * kk][2],     Sa[2 * kk][3]);
            php[kk][2] = packhi(Sa[2 * kk + 1][0], Sa[2 * kk + 1][1]);
            php[kk][3] = packhi(Sa[2 * kk + 1][2], Sa[2 * kk + 1][3]);
        }
        // O += P_hi * (V_hi + V_lo)
#pragma unroll
        for (int kk = 0; kk < 4; kk++)
#pragma unroll
            for (int j2 = 0; j2 < 4; j2++) {
                int r = kk * 16 + mrow;
                uint32_t d = (uint32_t)(r * 128 + SWZ16(r, j2 * 2 + mc) * 16);
                uint32_t vh[4], vl[4];
                ldsm_x4t(vh, stg + 2 * ARR + d);
                ldsm_x4t(vl, stg + 3 * ARR + d);
                mma_(Oa[2 * j2],     php[kk], vh[0], vh[1]);
                mma_(Oa[2 * j2],     php[kk], vl[0], vl[1]);
                mma_(Oa[2 * j2 + 1], php[kk], vh[2], vh[3]);
                mma_(Oa[2 * j2 + 1], php[kk], vl[2], vl[3]);
            }
        __syncthreads();
    }
    float inv0 = 1.f / lrr[0], inv1 = 1.f / lrr[1];
    int r = lane >> 2, q = (lane & 3) * 2;
    size_t o0 = qoff + (size_t)(warp * 16 + r) * Dc;
#pragma unroll
    for (int j = 0; j < 8; j++) {
        sst2(g_aoh, g_aol, o0 + j * 8 + q, Oa[j][0] * inv0, Oa[j][1] * inv0);
        sst2(g_aoh, g_aol, o0 + (size_t)8 * Dc + j * 8 + q, Oa[j][2] * inv1, Oa[j][3] * inv1);
    }
}

// ---------------- launch ----------------
extern "C" void kernel_launch(void* const* d_in, const int* in_sizes, int n_in,
                              void* d_out, int out_size) {
    const float* x_q  = (const float*)d_in[0];
    const int*   xidx = (const int*)d_in[1];
    const float* E    = (const float*)d_in[2];
    const float* rhos = (const float*)d_in[3];
    const float* Cs   = (const float*)d_in[4];
    const float* Wq   = (const float*)d_in[5];
    const float* Wk   = (const float*)d_in[6];
    const float* Wv   = (const float*)d_in[7];
    const float* Wo   = (const float*)d_in[8];
    const float* Wpe  = (const float*)d_in[9];
    const float* lnkg = (const float*)d_in[10];
    const float* lnkb = (const float*)d_in[11];
    const float* lnqg = (const float*)d_in[12];
    const float* lnqb = (const float*)d_in[13];
    float* out = (float*)d_out;

    bf16 *wqh, *wql, *woh, *wol, *memh, *meml, *xhh, *xhl, *Qh, *Ql, *aoh, *aol;
    cudaGetSymbolAddress((void**)&wqh, g_Wqh); cudaGetSymbolAddress((void**)&wql, g_Wql);
    cudaGetSymbolAddress((void**)&woh, g_Woh); cudaGetSymbolAddress((void**)&wol, g_Wol);
    cudaGetSymbolAddress((void**)&memh, g_memh); cudaGetSymbolAddress((void**)&meml, g_meml);
    cudaGetSymbolAddress((void**)&xhh, g_xhh); cudaGetSymbolAddress((void**)&xhl, g_xhl);
    cudaGetSymbolAddress((void**)&Qh, g_Qh); cudaGetSymbolAddress((void**)&Ql, g_Ql);
    cudaGetSymbolAddress((void**)&aoh, g_aoh); cudaGetSymbolAddress((void**)&aol, g_aol);

    const int gemm_smem = 8 * 128 * 80;   // 81920
    const int attn_smem = 98304;
    cudaFuncSetAttribute(gemm_bs<true>,  cudaFuncAttributeMaxDynamicSharedMemorySize, gemm_smem);
    cudaFuncSetAttribute(gemm_bs<false>, cudaFuncAttributeMaxDynamicSharedMemorySize, gemm_smem);
    cudaFuncSetAttribute(gemm_kv,        cudaFuncAttributeMaxDynamicSharedMemorySize, gemm_smem);
    cudaFuncSetAttribute(attn_kernel,    cudaFuncAttributeMaxDynamicSharedMemorySize, attn_smem);

    const int n2 = Dc * Dc / 2;
    split_w4_kernel<<<dim3(n2 / 256, 4), 256>>>(Wq, Wk, Wv, Wo);
    ln_rows_kernel<<<NSLOTc, 256>>>(E, lnkg, lnkb, memh, meml);
    ctab_kernel<<<(Sc * NSc + 255) / 256, 256>>>(rhos);

    // Q side first (big grids keep the chip busy)
    gateq_ln_kernel<<<Bc * Lc, 256>>>(x_q, Cs, Wpe, lnqg, lnqb);
    gemm_bs<true><<<dim3(Dc / 128, BLc / 128), 256, gemm_smem>>>(
        xhh, xhl, wqh, wql, nullptr, Qh, Ql, BLc, Dc, Dc);

    // fused K+V projection (64 blocks) then gather+gate
    gemm_kv<<<dim3(16, NSLOTc / 128), 256, gemm_smem>>>();
    gather_kernel<<<Bc * Sc, 256>>>(xidx, Wpe);

    attn_kernel<<<dim3(Lc / 128, Bc * Hc), 256, attn_smem>>>();

    gemm_bs<false><<<dim3(Dc / 128, BLc / 128), 256, gemm_smem>>>(
        aoh, aol, woh, wol, out, nullptr, nullptr, BLc, Dc, Dc);
}

// round 9
// speedup vs baseline: 2.9212x; 1.2156x over previous
#include <cuda_runtime.h>
#include <cuda_bf16.h>
#include <math.h>
#include <stdint.h>

#define Bc 2
#define Lc 2048
#define Sc 2048
#define Dc 1024
#define Hc 16
#define NSc 8
#define NSLOTc 512
#define HDc 64
#define BLc (Bc*Lc)
#define BSc (Bc*Sc)

typedef __nv_bfloat16 bf16;
typedef __nv_bfloat162 bf162;

// ---------------- scratch ----------------
__device__ __align__(16) bf16 g_Wqh[Dc*Dc], g_Wql[Dc*Dc];
__device__ __align__(16) bf16 g_Wkh[Dc*Dc], g_Wkl[Dc*Dc];
__device__ __align__(16) bf16 g_Wvh[Dc*Dc], g_Wvl[Dc*Dc];
__device__ __align__(16) bf16 g_Woh[Dc*Dc], g_Wol[Dc*Dc];
__device__ __align__(16) bf16 g_memh[NSLOTc*Dc], g_meml[NSLOTc*Dc];
__device__ __align__(16) float g_ek[NSLOTc*Dc], g_ev[NSLOTc*Dc];
__device__ __align__(16) float g_ctab[Sc*NSc];
__device__ __align__(16) float g_WpeT[NSc*Dc];
__device__ __align__(16) bf16 g_Kh[(size_t)BSc*Dc], g_Kl[(size_t)BSc*Dc];
__device__ __align__(16) bf16 g_Vh[(size_t)BSc*Dc], g_Vl[(size_t)BSc*Dc];
__device__ __align__(16) bf16 g_xhh[(size_t)BLc*Dc], g_xhl[(size_t)BLc*Dc];
__device__ __align__(16) bf16 g_Qh[(size_t)BLc*Dc], g_Ql[(size_t)BLc*Dc];
__device__ __align__(16) bf16 g_aoh[(size_t)BLc*Dc], g_aol[(size_t)BLc*Dc];

// ---------------- helpers ----------------
__device__ __forceinline__ uint32_t smem_u32(const void* p) {
    return (uint32_t)__cvta_generic_to_shared(p);
}
__device__ __forceinline__ void ldsm_x4(uint32_t* r, uint32_t a) {
    asm volatile("ldmatrix.sync.aligned.m8n8.x4.shared.b16 {%0,%1,%2,%3}, [%4];"
                 : "=r"(r[0]), "=r"(r[1]), "=r"(r[2]), "=r"(r[3]) : "r"(a));
}
__device__ __forceinline__ void ldsm_x4t(uint32_t* r, uint32_t a) {
    asm volatile("ldmatrix.sync.aligned.m8n8.x4.trans.shared.b16 {%0,%1,%2,%3}, [%4];"
                 : "=r"(r[0]), "=r"(r[1]), "=r"(r[2]), "=r"(r[3]) : "r"(a));
}
__device__ __forceinline__ void mma_(float* c, const uint32_t* a, uint32_t b0, uint32_t b1) {
    asm volatile("mma.sync.aligned.m16n8k16.row.col.f32.bf16.bf16.f32 "
                 "{%0,%1,%2,%3},{%4,%5,%6,%7},{%8,%9},{%0,%1,%2,%3};"
                 : "+f"(c[0]), "+f"(c[1]), "+f"(c[2]), "+f"(c[3])
                 : "r"(a[0]), "r"(a[1]), "r"(a[2]), "r"(a[3]), "r"(b0), "r"(b1));
}
__device__ __forceinline__ void mma3(float* c, const uint32_t* ah, const uint32_t* al,
                                     uint32_t bh0, uint32_t bh1, uint32_t bl0, uint32_t bl1) {
    mma_(c, ah, bh0, bh1); mma_(c, ah, bl0, bl1); mma_(c, al, bh0, bh1);
}
__device__ __forceinline__ void cpa16(uint32_t s, const void* g) {
    asm volatile("cp.async.cg.shared.global [%0], [%1], 16;" :: "r"(s), "l"(g));
}
__device__ __forceinline__ void cpa_commit() { asm volatile("cp.async.commit_group;"); }
__device__ __forceinline__ void sst2(bf16* H, bf16* L, size_t o, float x, float y) {
    bf162 h = __floats2bfloat162_rn(x, y);
    bf162 l = __floats2bfloat162_rn(x - __bfloat162float(h.x), y - __bfloat162float(h.y));
    *(bf162*)(H + o) = h; *(bf162*)(L + o) = l;
}
__device__ __forceinline__ void sst1(bf16* H, bf16* L, size_t o, float x) {
    bf16 h = __float2bfloat16_rn(x);
    H[o] = h; L[o] = __float2bfloat16_rn(x - __bfloat162float(h));
}
__device__ __forceinline__ void splitpack(float x, float y, uint32_t& h, uint32_t& l) {
    bf162 hh = __floats2bfloat162_rn(x, y);
    bf162 ll = __floats2bfloat162_rn(x - __bfloat162float(hh.x), y - __bfloat162float(hh.y));
    h = *(uint32_t*)&hh; l = *(uint32_t*)&ll;
}
__device__ __forceinline__ float blockReduceSum(float v, float* red) {
    int tid = threadIdx.x, lane = tid & 31, w = tid >> 5;
#pragma unroll
    for (int o = 16; o; o >>= 1) v += __shfl_xor_sync(0xffffffffu, v, o);
    if (lane == 0) red[w] = v;
    __syncthreads();
    if (tid == 0) {
        float s = 0.f;
#pragma unroll
        for (int i = 0; i < 8; i++) s += red[i];
        red[0] = s;
    }
    __syncthreads();
    float r = red[0];
    __syncthreads();
    return r;
}
#define SWZ16(r, c) ((c) ^ ((r) & 7))

// ---------------- elementwise kernels ----------------
// w==0 (Wq) pre-scaled by log2(e)/sqrt(HD) so softmax runs in base-2.
__global__ void split_w4_kernel(const float* __restrict__ Wq, const float* __restrict__ Wk,
                                const float* __restrict__ Wv, const float* __restrict__ Wo) {
    int w = blockIdx.y;
    int i = blockIdx.x * blockDim.x + threadIdx.x;
    const float* src = (w == 0) ? Wq : (w == 1) ? Wk : (w == 2) ? Wv : Wo;
    bf16* H = (w == 0) ? g_Wqh : (w == 1) ? g_Wkh : (w == 2) ? g_Wvh : g_Woh;
    bf16* L = (w == 0) ? g_Wql : (w == 1) ? g_Wkl : (w == 2) ? g_Wvl : g_Wol;
    float sc = (w == 0) ? 0.18033688011112042f : 1.0f;  // 0.125 * log2(e)
    float2 v = ((const float2*)src)[i];
    sst2(H, L, (size_t)i * 2, v.x * sc, v.y * sc);
}

__global__ void ln_rows_kernel(const float* __restrict__ X, const float* __restrict__ gw,
                               const float* __restrict__ bw,
                               bf16* __restrict__ Yh, bf16* __restrict__ Yl) {
    __shared__ float red[8];
    int r = blockIdx.x, tid = threadIdx.x;
    float4 x = *(const float4*)(X + (size_t)r * Dc + tid * 4);
    float mean = blockReduceSum(x.x + x.y + x.z + x.w, red) * (1.0f / Dc);
    float d0 = x.x - mean, d1 = x.y - mean, d2 = x.z - mean, d3 = x.w - mean;
    float var = blockReduceSum(d0*d0 + d1*d1 + d2*d2 + d3*d3, red) * (1.0f / Dc);
    float rs = rsqrtf(var + 1e-5f);
    float4 g4 = *(const float4*)(gw + tid * 4);
    float4 b4 = *(const float4*)(bw + tid * 4);
    size_t o = (size_t)r * Dc + tid * 4;
    sst2(Yh, Yl, o,     d0*rs*g4.x + b4.x, d1*rs*g4.y + b4.y);
    sst2(Yh, Yl, o + 2, d2*rs*g4.z + b4.z, d3*rs*g4.w + b4.w);
}

__global__ void ctab_kernel(const float* __restrict__ rhos) {
    int i = blockIdx.x * blockDim.x + threadIdx.x;
    if (i >= Sc * NSc) return;
    int s = i >> 3, m = i & 7;
    double age = (double)(Sc - 1 - s);
    g_ctab[i] = (float)exp(age * log((double)rhos[m]));
}

// Transpose Wpe[D,NS] -> g_WpeT[NS,D] (coalesced reads).
__global__ void wpet_kernel(const float* __restrict__ Wpe) {
    int i = blockIdx.x * blockDim.x + threadIdx.x;
    if (i >= Dc * NSc) return;
    g_WpeT[(i & 7) * Dc + (i >> 3)] = Wpe[i];
}

// gather + gate, strided-d assignment: thread t handles d = t, t+256, t+512, t+768.
// All WpeT / ek / ev accesses are warp-coalesced.
__global__ void gather_kernel(const int* __restrict__ xidx) {
    __shared__ float c[NSc];
    int bs = blockIdx.x, tid = threadIdx.x;
    int s = bs & (Sc - 1);
    int idx = xidx[bs];
    if (tid < NSc) c[tid] = g_ctab[s * NSc + tid];
    __syncthreads();
    float cc[NSc];
#pragma unroll
    for (int m = 0; m < NSc; m++) cc[m] = c[m];
    const float* ekr = g_ek + (size_t)idx * Dc;
    const float* evr = g_ev + (size_t)idx * Dc;
    size_t ob = (size_t)bs * Dc;
#pragma unroll
    for (int e = 0; e < 4; e++) {
        int d = e * 256 + tid;
        float t = 0.f;
#pragma unroll
        for (int m = 0; m < NSc; m++) t += cc[m] * g_WpeT[m * Dc + d];
        float g = t / (1.0f + __expf(-t));
        sst1(g_Kh, g_Kl, ob + d, ekr[d] * g);
        sst1(g_Vh, g_Vl, ob + d, evr[d] * g);
    }
}

// xh = ln_q(x_q * silu(C @ Wpe^T)), strided-d assignment, coalesced WpeT reads.
__global__ void gateq_ln_kernel(const float* __restrict__ xq, const float* __restrict__ Cs,
                                const float* __restrict__ gw, const float* __restrict__ bw) {
    __shared__ float red[8];
    __shared__ float c[NSc];
    int r = blockIdx.x, tid = threadIdx.x;
    if (tid < NSc) c[tid] = Cs[(size_t)r * NSc + tid];
    __syncthreads();
    float cc[NSc];
#pragma unroll
    for (int m = 0; m < NSc; m++) cc[m] = c[m];
    float y[4];
#pragma unroll
    for (int e = 0; e < 4; e++) {
        int d = e * 256 + tid;
        float t = 0.f;
#pragma unroll
        for (int m = 0; m < NSc; m++) t += cc[m] * g_WpeT[m * Dc + d];
        y[e] = xq[(size_t)r * Dc + d] * (t / (1.0f + __expf(-t)));
    }
    float mean = blockReduceSum(y[0] + y[1] + y[2] + y[3], red) * (1.0f / Dc);
#pragma unroll
    for (int e = 0; e < 4; e++) y[e] -= mean;
    float var = blockReduceSum(y[0]*y[0] + y[1]*y[1] + y[2]*y[2] + y[3]*y[3], red) * (1.0f / Dc);
    float rs = rsqrtf(var + 1e-5f);
#pragma unroll
    for (int e = 0; e < 4; e++) {
        int d = e * 256 + tid;
        sst1(g_xhh, g_xhl, (size_t)r * Dc + d, y[e] * rs * gw[d] + bw[d]);
    }
}

// ---------------- split-bf16 mma.sync GEMM core: C[tile] = A * B^T ----------------
// 128x128 tile, BK=32, 256 threads (8 warps 4m x 2n), double-buffered cp.async.
template<bool SPLITOUT>
__device__ __forceinline__
void gemm_core(const bf16* __restrict__ Ah, const bf16* __restrict__ Al,
               const bf16* __restrict__ Bh, const bf16* __restrict__ Bl,
               float* __restrict__ C, bf16* __restrict__ Ch, bf16* __restrict__ Cl,
               int N, int K, int row0, int col0, char* smraw) {
    const int RS = 80, TB = 128 * RS;
    int tid = threadIdx.x, lane = tid & 31, warp = tid >> 5;
    int wm = (warp >> 1) * 32, wn = (warp & 1) * 64;
    int r_ld = tid >> 1;
    const bf16* gp[4];
    gp[0] = Ah + (size_t)(row0 + r_ld) * K + (tid & 1) * 16;
    gp[1] = Al + (size_t)(row0 + r_ld) * K + (tid & 1) * 16;
    gp[2] = Bh + (size_t)(col0 + r_ld) * K + (tid & 1) * 16;
    gp[3] = Bl + (size_t)(col0 + r_ld) * K + (tid & 1) * 16;
    uint32_t sb = smem_u32(smraw);
    uint32_t st = (uint32_t)(r_ld * RS + (tid & 1) * 32);
    auto load = [&](int bf, int k0) {
#pragma unroll
        for (int o = 0; o < 4; o++) {
            uint32_t s = sb + (uint32_t)((bf * 4 + o) * TB) + st;
            cpa16(s, gp[o] + k0); cpa16(s + 16, gp[o] + k0 + 8);
        }
        cpa_commit();
    };
    float acc[2][8][4] = {};
    int mrow = lane & 15, mcb = (lane >> 4) * 16;
    const int KC = K / 32;
    load(0, 0);
    for (int kc = 0; kc < KC; kc++) {
        if (kc + 1 < KC) {
            load((kc + 1) & 1, (kc + 1) * 32);
            asm volatile("cp.async.wait_group 1;");
        } else {
            asm volatile("cp.async.wait_group 0;");
        }
        __syncthreads();
        uint32_t bo = sb + (uint32_t)((kc & 1) * 4 * TB);
#pragma unroll
        for (int ks = 0; ks < 2; ks++) {
            uint32_t ah[2][4], al[2][4];
#pragma unroll
            for (int i = 0; i < 2; i++) {
                uint32_t aa = bo + (uint32_t)((wm + i * 16 + mrow) * RS + ks * 32 + mcb);
                ldsm_x4(ah[i], aa); ldsm_x4(al[i], aa + TB);
            }
#pragma unroll
            for (int j2 = 0; j2 < 4; j2++) {
                uint32_t ba = bo + (uint32_t)(2 * TB + (wn + j2 * 16 + mrow) * RS + ks * 32 + mcb);
                uint32_t bh[4], bl[4];
                ldsm_x4(bh, ba); ldsm_x4(bl, ba + TB);
#pragma unroll
                for (int i = 0; i < 2; i++) {
                    mma3(acc[i][2 * j2],     ah[i], al[i], bh[0], bh[2], bl[0], bl[2]);
                    mma3(acc[i][2 * j2 + 1], ah[i], al[i], bh[1], bh[3], bl[1], bl[3]);
                }
            }
        }
        __syncthreads();
    }
    int r = lane >> 2, q = (lane & 3) * 2;
#pragma unroll
    for (int i = 0; i < 2; i++)
#pragma unroll
        for (int j = 0; j < 8; j++) {
            size_t g0 = (size_t)(row0 + wm + i * 16 + r) * N + col0 + wn + j * 8 + q;
            float* a = acc[i][j];
            if (SPLITOUT) {
                sst2(Ch, Cl, g0, a[0], a[1]);
                sst2(Ch, Cl, g0 + (size_t)8 * N, a[2], a[3]);
            } else {
                *(float2*)(C + g0) = make_float2(a[0], a[1]);
                *(float2*)(C + g0 + (size_t)8 * N) = make_float2(a[2], a[3]);
            }
        }
}

template<bool SPLITOUT>
__global__ __launch_bounds__(256)
void gemm_bs(const bf16* __restrict__ Ah, const bf16* __restrict__ Al,
             const bf16* __restrict__ Bh, const bf16* __restrict__ Bl,
             float* __restrict__ C, bf16* __restrict__ Ch, bf16* __restrict__ Cl,
             int M, int N, int K) {
    extern __shared__ char smraw[];
    gemm_core<SPLITOUT>(Ah, Al, Bh, Bl, C, Ch, Cl, N, K,
                        blockIdx.y * 128, blockIdx.x * 128, smraw);
}

// Fused K+V projection: blockIdx.x 0..7 -> Ek tile cols, 8..15 -> Ev tile cols.
__global__ __launch_bounds__(256)
void gemm_kv() {
    extern __shared__ char smraw[];
    int bx = blockIdx.x;
    if (bx < 8)
        gemm_core<false>(g_memh, g_meml, g_Wkh, g_Wkl, g_ek, nullptr, nullptr,
                         Dc, Dc, blockIdx.y * 128, bx * 128, smraw);
    else
        gemm_core<false>(g_memh, g_meml, g_Wvh, g_Wvl, g_ev, nullptr, nullptr,
                         Dc, Dc, blockIdx.y * 128, (bx - 8) * 128, smraw);
}

// ---------------- flash attention: 8 warps, 128-q tile, 2-stage pipeline, base-2 softmax ----------------
__global__ __launch_bounds__(256, 2)
void attn_kernel() {
    extern __shared__ char smraw[];
    uint32_t sb = smem_u32(smraw);
    const uint32_t QL = 16384, KV0 = 32768, STG = 32768, ARR = 8192;
    int tid = threadIdx.x, lane = tid & 31, warp = tid >> 5;
    int b = blockIdx.y >> 4, h = blockIdx.y & 15;
    int q0 = blockIdx.x * 128;
    size_t qoff = ((size_t)(b * Lc + q0)) * Dc + h * HDc;
    size_t koff = ((size_t)b * Sc) * Dc + h * HDc;
    {
        int r = tid >> 1, cb = (tid & 1) * 4;
        const bf16* q_h = g_Qh + qoff + (size_t)r * Dc;
        const bf16* q_l = g_Ql + qoff + (size_t)r * Dc;
#pragma unroll
        for (int j = 0; j < 4; j++) {
            int c = cb + j;
            uint32_t d = (uint32_t)(r * 128 + SWZ16(r, c) * 16);
            cpa16(sb + d, q_h + c * 8);
            cpa16(sb + QL + d, q_l + c * 8);
        }
        cpa_commit();
    }
    int kr = tid >> 2, kcb = (tid & 3) * 2;
    const bf16* gsrc[4] = {g_Kh + koff + (size_t)kr * Dc, g_Kl + koff + (size_t)kr * Dc,
                           g_Vh + koff + (size_t)kr * Dc, g_Vl + koff + (size_t)kr * Dc};
    uint32_t kdst[2];
#pragma unroll
    for (int j = 0; j < 2; j++)
        kdst[j] = (uint32_t)(kr * 128 + SWZ16(kr, kcb + j) * 16);
    auto loadKV = [&](int stage, int sc) {
        size_t go = (size_t)sc * 64 * Dc;
        uint32_t sbase = sb + KV0 + (uint32_t)stage * STG;
#pragma unroll
        for (int o = 0; o < 4; o++)
#pragma unroll
            for (int j = 0; j < 2; j++)
                cpa16(sbase + (uint32_t)(o * ARR) + kdst[j], gsrc[o] + go + (kcb + j) * 8);
        cpa_commit();
    };
    loadKV(0, 0);
    asm volatile("cp.async.wait_group 1;");
    __syncthreads();
    int mrow = lane & 15, mc = lane >> 4;
    uint32_t qh[4][4], ql[4][4];
#pragma unroll
    for (int ks = 0; ks < 4; ks++) {
        int r = warp * 16 + mrow;
        uint32_t d = (uint32_t)(r * 128 + SWZ16(r, ks * 2 + mc) * 16);
        ldsm_x4(qh[ks], sb + d);
        ldsm_x4(ql[ks], sb + QL + d);
    }
    float Oa[8][4] = {};
    float mr[2] = {-1e30f, -1e30f}, lrr[2] = {0.f, 0.f};
    const int NC = Sc / 64;
    for (int sc = 0; sc < NC; sc++) {
        if (sc + 1 < NC) {
            loadKV((sc + 1) & 1, sc + 1);
            asm volatile("cp.async.wait_group 1;");
        } else {
            asm volatile("cp.async.wait_group 0;");
        }
        __syncthreads();
        uint32_t stg = sb + KV0 + (uint32_t)((sc & 1) * STG);
        // S = Q K^T in base-2 log units (log2e/8 folded into Wq)
        float Sa[8][4] = {};
#pragma unroll
        for (int ks = 0; ks < 4; ks++)
#pragma unroll
            for (int j2 = 0; j2 < 4; j2++) {
                int r = j2 * 16 + mrow;
                uint32_t d = (uint32_t)(r * 128 + SWZ16(r, ks * 2 + mc) * 16);
                uint32_t bh[4], bl[4];
                ldsm_x4(bh, stg + d);
                ldsm_x4(bl, stg + ARR + d);
                mma3(Sa[2 * j2],     qh[ks], ql[ks], bh[0], bh[2], bl[0], bl[2]);
                mma3(Sa[2 * j2 + 1], qh[ks], ql[ks], bh[1], bh[3], bl[1], bl[3]);
            }
        // online softmax (base 2)
        float mx[2] = {-1e30f, -1e30f};
#pragma unroll
        for (int j = 0; j < 8; j++) {
            mx[0] = fmaxf(mx[0], fmaxf(Sa[j][0], Sa[j][1]));
            mx[1] = fmaxf(mx[1], fmaxf(Sa[j][2], Sa[j][3]));
        }
        float al2[2];
#pragma unroll
        for (int t = 0; t < 2; t++) {
            mx[t] = fmaxf(mx[t], __shfl_xor_sync(0xffffffffu, mx[t], 1));
            mx[t] = fmaxf(mx[t], __shfl_xor_sync(0xffffffffu, mx[t], 2));
            float nm = fmaxf(mr[t], mx[t]);
            al2[t] = exp2f(mr[t] - nm);
            mr[t] = nm;
        }
        float rs[2] = {0.f, 0.f};
#pragma unroll
        for (int j = 0; j < 8; j++) {
            Sa[j][0] = exp2f(Sa[j][0] - mr[0]); Sa[j][1] = exp2f(Sa[j][1] - mr[0]);
            Sa[j][2] = exp2f(Sa[j][2] - mr[1]); Sa[j][3] = exp2f(Sa[j][3] - mr[1]);
            rs[0] += Sa[j][0] + Sa[j][1]; rs[1] += Sa[j][2] + Sa[j][3];
            Oa[j][0] *= al2[0]; Oa[j][1] *= al2[0];
            Oa[j][2] *= al2[1]; Oa[j][3] *= al2[1];
        }
#pragma unroll
        for (int t = 0; t < 2; t++) {
            rs[t] += __shfl_xor_sync(0xffffffffu, rs[t], 1);
            rs[t] += __shfl_xor_sync(0xffffffffu, rs[t], 2);
            lrr[t] = lrr[t] * al2[t] + rs[t];
        }
        // pack P hi+lo first (Sa dies here, capping register pressure)
        uint32_t php[4][4], plp[4][4];
#pragma unroll
        for (int kk = 0; kk < 4; kk++) {
            splitpack(Sa[2 * kk][0],     Sa[2 * kk][1],     php[kk][0], plp[kk][0]);
            splitpack(Sa[2 * kk][2],     Sa[2 * kk][3],     php[kk][1], plp[kk][1]);
            splitpack(Sa[2 * kk + 1][0], Sa[2 * kk + 1][1], php[kk][2], plp[kk][2]);
            splitpack(Sa[2 * kk + 1][2], Sa[2 * kk + 1][3], php[kk][3], plp[kk][3]);
        }
        // O += Ph*Vh + Ph*Vl + Pl*Vh
#pragma unroll
        for (int kk = 0; kk < 4; kk++)
#pragma unroll
            for (int j2 = 0; j2 < 4; j2++) {
                int r = kk * 16 + mrow;
                uint32_t d = (uint32_t)(r * 128 + SWZ16(r, j2 * 2 + mc) * 16);
                uint32_t vh[4], vl[4];
                ldsm_x4t(vh, stg + 2 * ARR + d);
                ldsm_x4t(vl, stg + 3 * ARR + d);
                mma3(Oa[2 * j2],     php[kk], plp[kk], vh[0], vh[1], vl[0], vl[1]);
                mma3(Oa[2 * j2 + 1], php[kk], plp[kk], vh[2], vh[3], vl[2], vl[3]);
            }
        __syncthreads();
    }
    float inv0 = 1.f / lrr[0], inv1 = 1.f / lrr[1];
    int r = lane >> 2, q = (lane & 3) * 2;
    size_t o0 = qoff + (size_t)(warp * 16 + r) * Dc;
#pragma unroll
    for (int j = 0; j < 8; j++) {
        sst2(g_aoh, g_aol, o0 + j * 8 + q, Oa[j][0] * inv0, Oa[j][1] * inv0);
        sst2(g_aoh, g_aol, o0 + (size_t)8 * Dc + j * 8 + q, Oa[j][2] * inv1, Oa[j][3] * inv1);
    }
}

// ---------------- launch ----------------
extern "C" void kernel_launch(void* const* d_in, const int* in_sizes, int n_in,
                              void* d_out, int out_size) {
    const float* x_q  = (const float*)d_in[0];
    const int*   xidx = (const int*)d_in[1];
    const float* E    = (const float*)d_in[2];
    const float* rhos = (const float*)d_in[3];
    const float* Cs   = (const float*)d_in[4];
    const float* Wq   = (const float*)d_in[5];
    const float* Wk   = (const float*)d_in[6];
    const float* Wv   = (const float*)d_in[7];
    const float* Wo   = (const float*)d_in[8];
    const float* Wpe  = (const float*)d_in[9];
    const float* lnkg = (const float*)d_in[10];
    const float* lnkb = (const float*)d_in[11];
    const float* lnqg = (const float*)d_in[12];
    const float* lnqb = (const float*)d_in[13];
    float* out = (float*)d_out;

    bf16 *wqh, *wql, *woh, *wol, *memh, *meml, *xhh, *xhl, *Qh, *Ql, *aoh, *aol;
    cudaGetSymbolAddress((void**)&wqh, g_Wqh); cudaGetSymbolAddress((void**)&wql, g_Wql);
    cudaGetSymbolAddress((void**)&woh, g_Woh); cudaGetSymbolAddress((void**)&wol, g_Wol);
    cudaGetSymbolAddress((void**)&memh, g_memh); cudaGetSymbolAddress((void**)&meml, g_meml);
    cudaGetSymbolAddress((void**)&xhh, g_xhh); cudaGetSymbolAddress((void**)&xhl, g_xhl);
    cudaGetSymbolAddress((void**)&Qh, g_Qh); cudaGetSymbolAddress((void**)&Ql, g_Ql);
    cudaGetSymbolAddress((void**)&aoh, g_aoh); cudaGetSymbolAddress((void**)&aol, g_aol);

    const int gemm_smem = 8 * 128 * 80;   // 81920
    const int attn_smem = 98304;
    cudaFuncSetAttribute(gemm_bs<true>,  cudaFuncAttributeMaxDynamicSharedMemorySize, gemm_smem);
    cudaFuncSetAttribute(gemm_bs<false>, cudaFuncAttributeMaxDynamicSharedMemorySize, gemm_smem);
    cudaFuncSetAttribute(gemm_kv,        cudaFuncAttributeMaxDynamicSharedMemorySize, gemm_smem);
    cudaFuncSetAttribute(attn_kernel,    cudaFuncAttributeMaxDynamicSharedMemorySize, attn_smem);

    const int n2 = Dc * Dc / 2;
    split_w4_kernel<<<dim3(n2 / 256, 4), 256>>>(Wq, Wk, Wv, Wo);
    ln_rows_kernel<<<NSLOTc, 256>>>(E, lnkg, lnkb, memh, meml);
    ctab_kernel<<<(Sc * NSc + 255) / 256, 256>>>(rhos);
    wpet_kernel<<<(Dc * NSc + 255) / 256, 256>>>(Wpe);

    // Q side first (big grids keep the chip busy)
    gateq_ln_kernel<<<Bc * Lc, 256>>>(x_q, Cs, lnqg, lnqb);
    gemm_bs<true><<<dim3(Dc / 128, BLc / 128), 256, gemm_smem>>>(
        xhh, xhl, wqh, wql, nullptr, Qh, Ql, BLc, Dc, Dc);

    // fused K+V projection (64 blocks) then gather+gate
    gemm_kv<<<dim3(16, NSLOTc / 128), 256, gemm_smem>>>();
    gather_kernel<<<Bc * Sc, 256>>>(xidx);

    attn_kernel<<<dim3(Lc / 128, Bc * Hc), 256, attn_smem>>>();

    gemm_bs<false><<<dim3(Dc / 128, BLc / 128), 256, gemm_smem>>>(
        aoh, aol, woh, wol, out, nullptr, nullptr, BLc, Dc, Dc);
}